// round 2
// baseline (speedup 1.0000x reference)
#include <cuda_runtime.h>
#include <cuda_bf16.h>
#include <cstdint>

#define T_TOK 8192
#define H_DIM 2048
#define I_DIM 1408
#define E_NUM 8

// ---------------- scratch (device globals; no allocations) ----------------
__device__ int   d_count[E_NUM];
__device__ int   d_cursor[E_NUM];
__device__ int   d_off[E_NUM];
__device__ int   d_tok_e[T_TOK * 2];
__device__ float d_tok_w[T_TOK * 2];
__device__ int   d_pair_slot[T_TOK * 2];   // tok*2 + k
__device__ float d_pair_w[T_TOK * 2];
__device__ float d_hact[(size_t)T_TOK * 2 * I_DIM];   // 92 MB activation scratch

// ---------------- helpers ----------------
static __device__ __forceinline__ uint32_t smem_u32(const void* p) {
    return (uint32_t)__cvta_generic_to_shared(p);
}

static __device__ __forceinline__ void ldsm4(uint32_t& r0, uint32_t& r1, uint32_t& r2, uint32_t& r3, uint32_t a) {
    asm volatile("ldmatrix.sync.aligned.m8n8.x4.shared.b16 {%0,%1,%2,%3},[%4];"
                 : "=r"(r0), "=r"(r1), "=r"(r2), "=r"(r3) : "r"(a));
}
static __device__ __forceinline__ void ldsm4t(uint32_t& r0, uint32_t& r1, uint32_t& r2, uint32_t& r3, uint32_t a) {
    asm volatile("ldmatrix.sync.aligned.m8n8.x4.trans.shared.b16 {%0,%1,%2,%3},[%4];"
                 : "=r"(r0), "=r"(r1), "=r"(r2), "=r"(r3) : "r"(a));
}
static __device__ __forceinline__ void mma_bf16(float* c, const uint32_t* a, const uint32_t* b) {
    asm volatile("mma.sync.aligned.m16n8k16.row.col.f32.bf16.bf16.f32 "
                 "{%0,%1,%2,%3},{%4,%5,%6,%7},{%8,%9},{%0,%1,%2,%3};"
                 : "+f"(c[0]), "+f"(c[1]), "+f"(c[2]), "+f"(c[3])
                 : "r"(a[0]), "r"(a[1]), "r"(a[2]), "r"(a[3]), "r"(b[0]), "r"(b[1]));
}
static __device__ __forceinline__ void split_bf16(float f, __nv_bfloat16& hi, __nv_bfloat16& lo) {
    hi = __float2bfloat16(f);
    lo = __float2bfloat16(f - __bfloat162float(hi));
}

// ---------------- K0: zero out + counters ----------------
__global__ void k_zero(float* __restrict__ out) {
    size_t n4 = (size_t)T_TOK * H_DIM / 4;
    float4 z = make_float4(0.f, 0.f, 0.f, 0.f);
    for (size_t i = (size_t)blockIdx.x * blockDim.x + threadIdx.x; i < n4; i += (size_t)gridDim.x * blockDim.x)
        ((float4*)out)[i] = z;
    if (blockIdx.x == 0 && threadIdx.x < E_NUM) d_count[threadIdx.x] = 0;
}

// ---------------- K1: router (warp per token) ----------------
__global__ void k_router(const float* __restrict__ x, const float* __restrict__ gw) {
    int warp = (blockIdx.x * blockDim.x + threadIdx.x) >> 5;
    int lane = threadIdx.x & 31;
    if (warp >= T_TOK) return;
    const float* xr = x + (size_t)warp * H_DIM;
    float acc[E_NUM];
#pragma unroll
    for (int e = 0; e < E_NUM; e++) acc[e] = 0.f;
    for (int i = lane; i < H_DIM; i += 32) {
        float xv = xr[i];
#pragma unroll
        for (int e = 0; e < E_NUM; e++) acc[e] += xv * gw[e * H_DIM + i];
    }
#pragma unroll
    for (int e = 0; e < E_NUM; e++)
#pragma unroll
        for (int o = 16; o > 0; o >>= 1) acc[e] += __shfl_xor_sync(0xffffffffu, acc[e], o);
    if (lane == 0) {
        float m = acc[0];
#pragma unroll
        for (int e = 1; e < E_NUM; e++) m = fmaxf(m, acc[e]);
        float p[E_NUM];
#pragma unroll
        for (int e = 0; e < E_NUM; e++) p[e] = __expf(acc[e] - m);
        int e0 = 0; float w0 = p[0];
#pragma unroll
        for (int e = 1; e < E_NUM; e++) if (p[e] > w0) { w0 = p[e]; e0 = e; }
        int e1 = -1; float w1 = -1.f;
#pragma unroll
        for (int e = 0; e < E_NUM; e++) if (e != e0 && p[e] > w1) { w1 = p[e]; e1 = e; }
        float inv = 1.f / (w0 + w1);   // softmax denominator cancels in top-k renorm
        d_tok_e[warp * 2 + 0] = e0; d_tok_w[warp * 2 + 0] = w0 * inv;
        d_tok_e[warp * 2 + 1] = e1; d_tok_w[warp * 2 + 1] = w1 * inv;
        atomicAdd(&d_count[e0], 1);
        atomicAdd(&d_count[e1], 1);
    }
}

// ---------------- K2: exclusive scan of counts ----------------
__global__ void k_scan() {
    if (threadIdx.x == 0) {
        int c = 0;
        for (int e = 0; e < E_NUM; e++) { d_off[e] = c; c += d_count[e]; d_cursor[e] = 0; }
    }
}

// ---------------- K3: fill per-expert pair lists ----------------
__global__ void k_fill() {
    int t = blockIdx.x * blockDim.x + threadIdx.x;
    if (t >= T_TOK) return;
#pragma unroll
    for (int k = 0; k < 2; k++) {
        int e = d_tok_e[t * 2 + k];
        int pos = atomicAdd(&d_cursor[e], 1);
        int p = d_off[e] + pos;
        d_pair_slot[p] = t * 2 + k;
        d_pair_w[p] = d_tok_w[t * 2 + k];
    }
}

// ---------------- MMA core macro (bf16x3 over one BK=32 slab) ----------------
#define MMA_SLAB()                                                                      \
    _Pragma("unroll")                                                                   \
    for (int kk = 0; kk < 32; kk += 16) {                                               \
        uint32_t afr[4][4], bh[4][2], bl[4][2];                                         \
        _Pragma("unroll")                                                               \
        for (int p = 0; p < 2; p++) {                                                   \
            int mtx = lane >> 3;                                                        \
            int krow = kk + (mtx & 1) * 8 + (lane & 7);                                 \
            int ncol = wn + p * 16 + (mtx >> 1) * 8;                                    \
            uint32_t r0, r1, r2, r3;                                                    \
            ldsm4t(r0, r1, r2, r3, smem_u32(&sBh[krow][ncol]));                         \
            bh[p * 2][0] = r0; bh[p * 2][1] = r1; bh[p * 2 + 1][0] = r2; bh[p * 2 + 1][1] = r3; \
            ldsm4t(r0, r1, r2, r3, smem_u32(&sBl[krow][ncol]));                         \
            bl[p * 2][0] = r0; bl[p * 2][1] = r1; bl[p * 2 + 1][0] = r2; bl[p * 2 + 1][1] = r3; \
        }                                                                               \
        _Pragma("unroll")                                                               \
        for (int mi = 0; mi < 4; mi++) {                                                \
            int row = wm + mi * 16 + (lane & 15);                                       \
            int col = kk + (lane >> 4) * 8;                                             \
            ldsm4(afr[mi][0], afr[mi][1], afr[mi][2], afr[mi][3], smem_u32(&sAh[row][col])); \
        }                                                                               \
        _Pragma("unroll")                                                               \
        for (int mi = 0; mi < 4; mi++)                                                  \
            _Pragma("unroll")                                                           \
            for (int ni = 0; ni < 4; ni++) {                                            \
                mma_bf16(acc[mi][ni], afr[mi], bh[ni]);                                 \
                mma_bf16(acc[mi][ni], afr[mi], bl[ni]);                                 \
            }                                                                           \
        _Pragma("unroll")                                                               \
        for (int mi = 0; mi < 4; mi++) {                                                \
            int row = wm + mi * 16 + (lane & 15);                                       \
            int col = kk + (lane >> 4) * 8;                                             \
            ldsm4(afr[mi][0], afr[mi][1], afr[mi][2], afr[mi][3], smem_u32(&sAl[row][col])); \
        }                                                                               \
        _Pragma("unroll")                                                               \
        for (int mi = 0; mi < 4; mi++)                                                  \
            _Pragma("unroll")                                                           \
            for (int ni = 0; ni < 4; ni++)                                              \
                mma_bf16(acc[mi][ni], afr[mi], bh[ni]);                                 \
    }

// ---------------- K4: GEMM1 — gathered X @ [Wgate ⧉ Wup] + SiLU·up ----------------
__global__ void __launch_bounds__(256, 2) k_gemm1(const float* __restrict__ x,
                                                  const float* __restrict__ wgate,
                                                  const float* __restrict__ wup) {
    __shared__ __align__(16) __nv_bfloat16 sAh[128][40], sAl[128][40];
    __shared__ __align__(16) __nv_bfloat16 sBh[32][136], sBl[32][136];
    __shared__ int sTok[128];

    int e = blockIdx.z;
    int cnt = d_count[e];
    int rowbase = blockIdx.y * 128;
    if (rowbase >= cnt) return;
    int off = d_off[e];
    int ct = blockIdx.x;                 // 64 h-columns per tile
    int tid = threadIdx.x;

    if (tid < 128) {
        int gr = rowbase + tid;
        sTok[tid] = (gr < cnt) ? (d_pair_slot[off + gr] >> 1) : -1;
    }
    int warp = tid >> 5, lane = tid & 31;
    int wm = (warp & 1) * 64, wn = (warp >> 1) * 32;

    float acc[4][4][4];
#pragma unroll
    for (int mi = 0; mi < 4; mi++)
#pragma unroll
        for (int ni = 0; ni < 4; ni++)
#pragma unroll
            for (int j = 0; j < 4; j++) acc[mi][ni][j] = 0.f;

    const float* gbase = wgate + (size_t)e * H_DIM * I_DIM + ct * 64;
    const float* ubase = wup   + (size_t)e * H_DIM * I_DIM + ct * 64;

    for (int kb = 0; kb < H_DIM / 32; kb++) {
        int k0 = kb * 32;
        __syncthreads();
        // A: gathered x rows, fp32 -> (hi, lo) bf16
#pragma unroll
        for (int it = 0; it < 4; it++) {
            int idx = tid + it * 256;
            int r = idx >> 3, f4 = idx & 7;
            int tok = sTok[r];
            float4 v = (tok >= 0) ? __ldg((const float4*)(x + (size_t)tok * H_DIM + k0 + f4 * 4))
                                  : make_float4(0.f, 0.f, 0.f, 0.f);
            float vv[4] = {v.x, v.y, v.z, v.w};
#pragma unroll
            for (int j = 0; j < 4; j++) {
                __nv_bfloat16 h, l; split_bf16(vv[j], h, l);
                sAh[r][f4 * 4 + j] = h; sAl[r][f4 * 4 + j] = l;
            }
        }
        // B: interleave gate (even cols) / up (odd cols)
#pragma unroll
        for (int it = 0; it < 4; it++) {
            int idx = tid + it * 256;
            int f4i = idx & 31, r = idx >> 5;
            int isUp = f4i >> 4, c4 = f4i & 15;
            const float* src = isUp ? ubase : gbase;
            float4 v = __ldg((const float4*)(src + (size_t)(k0 + r) * I_DIM + c4 * 4));
            float vv[4] = {v.x, v.y, v.z, v.w};
#pragma unroll
            for (int j = 0; j < 4; j++) {
                int n = ((c4 * 4 + j) << 1) | isUp;
                __nv_bfloat16 h, l; split_bf16(vv[j], h, l);
                sBh[r][n] = h; sBl[r][n] = l;
            }
        }
        __syncthreads();
        MMA_SLAB();
    }

    // epilogue: (c0,c1) = (gate, up) at the same h column -> SiLU(gate)*up
#pragma unroll
    for (int mi = 0; mi < 4; mi++) {
        int gr0 = rowbase + wm + mi * 16 + (lane >> 2);
        int gr1 = gr0 + 8;
#pragma unroll
        for (int ni = 0; ni < 4; ni++) {
            int ncol = wn + ni * 8 + (lane & 3) * 2;
            int hc = ct * 64 + (ncol >> 1);
            if (gr0 < cnt) {
                float g = acc[mi][ni][0], u = acc[mi][ni][1];
                d_hact[(size_t)(off + gr0) * I_DIM + hc] = u * g / (1.f + __expf(-g));
            }
            if (gr1 < cnt) {
                float g = acc[mi][ni][2], u = acc[mi][ni][3];
                d_hact[(size_t)(off + gr1) * I_DIM + hc] = u * g / (1.f + __expf(-g));
            }
        }
    }
}

// ---------------- K5: GEMM2 — h @ Wdown, scaled combine via 2 deterministic atomics ----------------
__global__ void __launch_bounds__(256, 2) k_gemm2(const float* __restrict__ wdown,
                                                  float* __restrict__ out) {
    __shared__ __align__(16) __nv_bfloat16 sAh[128][40], sAl[128][40];
    __shared__ __align__(16) __nv_bfloat16 sBh[32][136], sBl[32][136];
    __shared__ int sSlot[128];
    __shared__ float sW[128];

    int e = blockIdx.z;
    int cnt = d_count[e];
    int rowbase = blockIdx.y * 128;
    if (rowbase >= cnt) return;
    int off = d_off[e];
    int nt = blockIdx.x;
    int tid = threadIdx.x;

    if (tid < 128) {
        int gr = rowbase + tid;
        if (gr < cnt) { sSlot[tid] = d_pair_slot[off + gr]; sW[tid] = d_pair_w[off + gr]; }
        else          { sSlot[tid] = 0;                     sW[tid] = 0.f; }
    }
    int warp = tid >> 5, lane = tid & 31;
    int wm = (warp & 1) * 64, wn = (warp >> 1) * 32;

    float acc[4][4][4];
#pragma unroll
    for (int mi = 0; mi < 4; mi++)
#pragma unroll
        for (int ni = 0; ni < 4; ni++)
#pragma unroll
            for (int j = 0; j < 4; j++) acc[mi][ni][j] = 0.f;

    const float* abase = d_hact + (size_t)(off + rowbase) * I_DIM;
    const float* bbase = wdown + (size_t)e * I_DIM * H_DIM + nt * 128;

    for (int kb = 0; kb < I_DIM / 32; kb++) {
        int k0 = kb * 32;
        __syncthreads();
#pragma unroll
        for (int it = 0; it < 4; it++) {
            int idx = tid + it * 256;
            int r = idx >> 3, f4 = idx & 7;
            float4 v = ((rowbase + r) < cnt) ? __ldg((const float4*)(abase + (size_t)r * I_DIM + k0 + f4 * 4))
                                             : make_float4(0.f, 0.f, 0.f, 0.f);
            float vv[4] = {v.x, v.y, v.z, v.w};
#pragma unroll
            for (int j = 0; j < 4; j++) {
                __nv_bfloat16 h, l; split_bf16(vv[j], h, l);
                sAh[r][f4 * 4 + j] = h; sAl[r][f4 * 4 + j] = l;
            }
        }
#pragma unroll
        for (int it = 0; it < 4; it++) {
            int idx = tid + it * 256;
            int c4 = idx & 31, r = idx >> 5;
            float4 v = __ldg((const float4*)(bbase + (size_t)(k0 + r) * H_DIM + c4 * 4));
            float vv[4] = {v.x, v.y, v.z, v.w};
#pragma unroll
            for (int j = 0; j < 4; j++) {
                __nv_bfloat16 h, l; split_bf16(vv[j], h, l);
                sBh[r][c4 * 4 + j] = h; sBl[r][c4 * 4 + j] = l;
            }
        }
        __syncthreads();
        MMA_SLAB();
    }

#pragma unroll
    for (int mi = 0; mi < 4; mi++) {
        int lr0 = wm + mi * 16 + (lane >> 2);
        int lr1 = lr0 + 8;
        int gr0 = rowbase + lr0, gr1 = rowbase + lr1;
        int tok0 = sSlot[lr0] >> 1; float w0 = sW[lr0];
        int tok1 = sSlot[lr1] >> 1; float w1 = sW[lr1];
#pragma unroll
        for (int ni = 0; ni < 4; ni++) {
            int col = nt * 128 + wn + ni * 8 + (lane & 3) * 2;
            if (gr0 < cnt) {
                atomicAdd(&out[(size_t)tok0 * H_DIM + col],     acc[mi][ni][0] * w0);
                atomicAdd(&out[(size_t)tok0 * H_DIM + col + 1], acc[mi][ni][1] * w0);
            }
            if (gr1 < cnt) {
                atomicAdd(&out[(size_t)tok1 * H_DIM + col],     acc[mi][ni][2] * w1);
                atomicAdd(&out[(size_t)tok1 * H_DIM + col + 1], acc[mi][ni][3] * w1);
            }
        }
    }
}

// ---------------- launch ----------------
extern "C" void kernel_launch(void* const* d_in, const int* in_sizes, int n_in,
                              void* d_out, int out_size) {
    const float* x  = (const float*)d_in[0];   // [T, H]
    const float* gw = (const float*)d_in[1];   // [E, H]
    const float* wg = (const float*)d_in[2];   // [E, H, I]
    const float* wu = (const float*)d_in[3];   // [E, H, I]
    const float* wd = (const float*)d_in[4];   // [E, I, H]
    float* out = (float*)d_out;                // [T, H]

    k_zero<<<2048, 256>>>(out);
    k_router<<<T_TOK / 8, 256>>>(x, gw);
    k_scan<<<1, 32>>>();
    k_fill<<<T_TOK / 256, 256>>>();
    dim3 g1(I_DIM / 64, T_TOK / 128, E_NUM);   // (22, 64, 8), early-exit beyond count
    k_gemm1<<<g1, 256>>>(x, wg, wu);
    dim3 g2(H_DIM / 128, T_TOK / 128, E_NUM);  // (16, 64, 8)
    k_gemm2<<<g2, 256>>>(wd, out);
}

// round 5
// speedup vs baseline: 1.2514x; 1.2514x over previous
#include <cuda_runtime.h>
#include <cuda_bf16.h>
#include <cstdint>

#define T_TOK 8192
#define H_DIM 2048
#define I_DIM 1408
#define E_NUM 8
#define NI2   (2 * I_DIM)   // 2816 interleaved gate/up columns

// ---------------- scratch (device globals; no allocations) ----------------
__device__ int   d_count[E_NUM];
__device__ int   d_cursor[E_NUM];
__device__ int   d_off[E_NUM];
__device__ int   d_tok_e[T_TOK * 2];
__device__ float d_tok_w[T_TOK * 2];
__device__ int   d_pos[T_TOK * 2];          // token,k -> compacted pair position
__device__ int   d_pair_slot[T_TOK * 2];    // compacted: tok*2+k

__device__ __align__(16) __nv_bfloat16 d_xhi[(size_t)T_TOK * H_DIM];
__device__ __align__(16) __nv_bfloat16 d_xlo[(size_t)T_TOK * H_DIM];
__device__ __align__(16) __nv_bfloat16 d_w1hi[(size_t)E_NUM * NI2 * H_DIM];
__device__ __align__(16) __nv_bfloat16 d_w1lo[(size_t)E_NUM * NI2 * H_DIM];
__device__ __align__(16) __nv_bfloat16 d_w2hi[(size_t)E_NUM * H_DIM * I_DIM];
__device__ __align__(16) __nv_bfloat16 d_w2lo[(size_t)E_NUM * H_DIM * I_DIM];
__device__ __align__(16) __nv_bfloat16 d_hhi[(size_t)T_TOK * 2 * I_DIM];
__device__ __align__(16) __nv_bfloat16 d_hlo[(size_t)T_TOK * 2 * I_DIM];
__device__ __align__(16) float         d_y[(size_t)T_TOK * 2 * H_DIM];

// ---------------- helpers ----------------
static __device__ __forceinline__ uint32_t smem_u32(const void* p) {
    return (uint32_t)__cvta_generic_to_shared(p);
}
static __device__ __forceinline__ void ldsm4(uint32_t& r0, uint32_t& r1, uint32_t& r2, uint32_t& r3, uint32_t a) {
    asm volatile("ldmatrix.sync.aligned.m8n8.x4.shared.b16 {%0,%1,%2,%3},[%4];"
                 : "=r"(r0), "=r"(r1), "=r"(r2), "=r"(r3) : "r"(a));
}
static __device__ __forceinline__ void mma_bf16(float* c, const uint32_t* a, const uint32_t* b) {
    asm volatile("mma.sync.aligned.m16n8k16.row.col.f32.bf16.bf16.f32 "
                 "{%0,%1,%2,%3},{%4,%5,%6,%7},{%8,%9},{%0,%1,%2,%3};"
                 : "+f"(c[0]), "+f"(c[1]), "+f"(c[2]), "+f"(c[3])
                 : "r"(a[0]), "r"(a[1]), "r"(a[2]), "r"(a[3]), "r"(b[0]), "r"(b[1]));
}
static __device__ __forceinline__ void cpa16(uint32_t s, const void* g, int sz) {
    asm volatile("cp.async.cg.shared.global [%0], [%1], 16, %2;" :: "r"(s), "l"(g), "r"(sz));
}
static __device__ __forceinline__ void split_bf16(float f, __nv_bfloat16& hi, __nv_bfloat16& lo) {
    hi = __float2bfloat16(f);
    lo = __float2bfloat16(f - __bfloat162float(hi));
}

// smem geometry: 4 arrays per stage (Ah, Al, Bh, Bl), each 128 rows x 32 bf16, 80B pitch
#define PITCHB      80
#define ARR_BYTES   (128 * PITCHB)            // 10240
#define STAGE_BYTES (4 * ARR_BYTES)           // 40960
#define SMEM_DYN    (512 + 2 * STAGE_BYTES)   // sTok + 2 stages = 82432

// ---------------- pre-pass: x -> bf16 hi/lo; zero counters ----------------
__global__ void k_convx(const float* __restrict__ x) {
    if (blockIdx.x == 0 && threadIdx.x < E_NUM) d_count[threadIdx.x] = 0;
    size_t idx = (size_t)blockIdx.x * 256 + threadIdx.x;        // one float4
    float4 v = ((const float4*)x)[idx];
    float f[4] = {v.x, v.y, v.z, v.w};
    __nv_bfloat16 h[4], l[4];
#pragma unroll
    for (int j = 0; j < 4; j++) split_bf16(f[j], h[j], l[j]);
    ((__nv_bfloat162*)d_xhi)[2 * idx + 0] = __halves2bfloat162(h[0], h[1]);
    ((__nv_bfloat162*)d_xhi)[2 * idx + 1] = __halves2bfloat162(h[2], h[3]);
    ((__nv_bfloat162*)d_xlo)[2 * idx + 0] = __halves2bfloat162(l[0], l[1]);
    ((__nv_bfloat162*)d_xlo)[2 * idx + 1] = __halves2bfloat162(l[2], l[3]);
}

// ---------------- pre-pass: W1 transpose+interleave -> [e][2i+mat][H] hi/lo ----------------
__global__ void k_w1t(const float* __restrict__ wg, const float* __restrict__ wu) {
    __shared__ float tile[32][33];
    int mat = blockIdx.z & 1, e = blockIdx.z >> 1;
    const float* src = (mat ? wu : wg) + (size_t)e * H_DIM * I_DIM;
    int i0 = blockIdx.x * 32, h0 = blockIdx.y * 32;
    int tx = threadIdx.x, ty = threadIdx.y;
#pragma unroll
    for (int j = 0; j < 4; j++)
        tile[ty + 8 * j][tx] = src[(size_t)(h0 + ty + 8 * j) * I_DIM + i0 + tx];
    __syncthreads();
#pragma unroll
    for (int j = 0; j < 4; j++) {
        int oi = i0 + ty + 8 * j, oh = h0 + tx;
        float v = tile[tx][ty + 8 * j];
        __nv_bfloat16 hb, lb; split_bf16(v, hb, lb);
        size_t o = ((size_t)e * NI2 + 2 * oi + mat) * H_DIM + oh;
        d_w1hi[o] = hb; d_w1lo[o] = lb;
    }
}

// ---------------- pre-pass: Wdown transpose -> [e][h][i] hi/lo ----------------
__global__ void k_w2t(const float* __restrict__ wd) {
    __shared__ float tile[32][33];
    int e = blockIdx.z;
    const float* src = wd + (size_t)e * I_DIM * H_DIM;
    int h0 = blockIdx.x * 32, i0 = blockIdx.y * 32;
    int tx = threadIdx.x, ty = threadIdx.y;
#pragma unroll
    for (int j = 0; j < 4; j++)
        tile[ty + 8 * j][tx] = src[(size_t)(i0 + ty + 8 * j) * H_DIM + h0 + tx];
    __syncthreads();
#pragma unroll
    for (int j = 0; j < 4; j++) {
        int oh = h0 + ty + 8 * j, oi = i0 + tx;
        float v = tile[tx][ty + 8 * j];
        __nv_bfloat16 hb, lb; split_bf16(v, hb, lb);
        size_t o = ((size_t)e * H_DIM + oh) * I_DIM + oi;
        d_w2hi[o] = hb; d_w2lo[o] = lb;
    }
}

// ---------------- router (warp per token, fp32 for exact top-k) ----------------
__global__ void k_router(const float* __restrict__ x, const float* __restrict__ gw) {
    int warp = (blockIdx.x * blockDim.x + threadIdx.x) >> 5;
    int lane = threadIdx.x & 31;
    if (warp >= T_TOK) return;
    const float* xr = x + (size_t)warp * H_DIM;
    float acc[E_NUM];
#pragma unroll
    for (int e = 0; e < E_NUM; e++) acc[e] = 0.f;
    for (int i = lane; i < H_DIM; i += 32) {
        float xv = xr[i];
#pragma unroll
        for (int e = 0; e < E_NUM; e++) acc[e] += xv * gw[e * H_DIM + i];
    }
#pragma unroll
    for (int e = 0; e < E_NUM; e++)
#pragma unroll
        for (int o = 16; o > 0; o >>= 1) acc[e] += __shfl_xor_sync(0xffffffffu, acc[e], o);
    if (lane == 0) {
        float m = acc[0];
#pragma unroll
        for (int e = 1; e < E_NUM; e++) m = fmaxf(m, acc[e]);
        float p[E_NUM];
#pragma unroll
        for (int e = 0; e < E_NUM; e++) p[e] = __expf(acc[e] - m);
        int e0 = 0; float w0 = p[0];
#pragma unroll
        for (int e = 1; e < E_NUM; e++) if (p[e] > w0) { w0 = p[e]; e0 = e; }
        int e1 = -1; float w1 = -1.f;
#pragma unroll
        for (int e = 0; e < E_NUM; e++) if (e != e0 && p[e] > w1) { w1 = p[e]; e1 = e; }
        float inv = 1.f / (w0 + w1);
        d_tok_e[warp * 2 + 0] = e0; d_tok_w[warp * 2 + 0] = w0 * inv;
        d_tok_e[warp * 2 + 1] = e1; d_tok_w[warp * 2 + 1] = w1 * inv;
        atomicAdd(&d_count[e0], 1);
        atomicAdd(&d_count[e1], 1);
    }
}

__global__ void k_scan() {
    if (threadIdx.x == 0) {
        int c = 0;
        for (int e = 0; e < E_NUM; e++) { d_off[e] = c; c += d_count[e]; d_cursor[e] = 0; }
    }
}

__global__ void k_fill() {
    int t = blockIdx.x * blockDim.x + threadIdx.x;
    if (t >= T_TOK) return;
#pragma unroll
    for (int k = 0; k < 2; k++) {
        int e = d_tok_e[t * 2 + k];
        int pos = atomicAdd(&d_cursor[e], 1);
        int p = d_off[e] + pos;
        d_pair_slot[p] = t * 2 + k;
        d_pos[t * 2 + k] = p;
    }
}

// ---------------- MMA over one 32-K smem stage (bf16x3), warp tile 64x32 ----------------
// A arrays: [m][k] 80B pitch; B arrays: [n][k] 80B pitch. Non-trans ldmatrix for both.
#define COMPUTE_SLAB(pAh, pAl, pBh, pBl)                                                \
    _Pragma("unroll")                                                                   \
    for (int kk = 0; kk < 32; kk += 16) {                                               \
        uint32_t afr[4][4], bh[4][2], bl[4][2];                                         \
        _Pragma("unroll")                                                               \
        for (int p = 0; p < 2; p++) {                                                   \
            int bn = wn + p * 16 + ((lane >> 4) << 3) + (lane & 7);                     \
            int bk = kk + ((lane >> 3) & 1) * 8;                                        \
            uint32_t r0, r1, r2, r3;                                                    \
            ldsm4(r0, r1, r2, r3, smem_u32(pBh + bn * PITCHB + bk * 2));                \
            bh[p * 2][0] = r0; bh[p * 2][1] = r1;                                       \
            bh[p * 2 + 1][0] = r2; bh[p * 2 + 1][1] = r3;                               \
            ldsm4(r0, r1, r2, r3, smem_u32(pBl + bn * PITCHB + bk * 2));                \
            bl[p * 2][0] = r0; bl[p * 2][1] = r1;                                       \
            bl[p * 2 + 1][0] = r2; bl[p * 2 + 1][1] = r3;                               \
        }                                                                               \
        _Pragma("unroll")                                                               \
        for (int mi = 0; mi < 4; mi++) {                                                \
            int row = wm + mi * 16 + (lane & 15);                                       \
            int col = kk + (lane >> 4) * 8;                                             \
            ldsm4(afr[mi][0], afr[mi][1], afr[mi][2], afr[mi][3],                       \
                  smem_u32(pAh + row * PITCHB + col * 2));                              \
        }                                                                               \
        _Pragma("unroll")                                                               \
        for (int mi = 0; mi < 4; mi++)                                                  \
            _Pragma("unroll")                                                           \
            for (int ni = 0; ni < 4; ni++) {                                            \
                mma_bf16(acc[mi][ni], afr[mi], bh[ni]);                                 \
                mma_bf16(acc[mi][ni], afr[mi], bl[ni]);                                 \
            }                                                                           \
        _Pragma("unroll")                                                               \
        for (int mi = 0; mi < 4; mi++) {                                                \
            int row = wm + mi * 16 + (lane & 15);                                       \
            int col = kk + (lane >> 4) * 8;                                             \
            ldsm4(afr[mi][0], afr[mi][1], afr[mi][2], afr[mi][3],                       \
                  smem_u32(pAl + row * PITCHB + col * 2));                              \
        }                                                                               \
        _Pragma("unroll")                                                               \
        for (int mi = 0; mi < 4; mi++)                                                  \
            _Pragma("unroll")                                                           \
            for (int ni = 0; ni < 4; ni++)                                              \
                mma_bf16(acc[mi][ni], afr[mi], bh[ni]);                                 \
    }

// ---------------- GEMM1: gathered X @ [Wgate ⧉ Wup] -> h (SiLU*up) ----------------
__global__ void __launch_bounds__(256, 2) k_gemm1() {
    extern __shared__ char smem[];
    int e = blockIdx.z;
    int cnt = d_count[e];
    int rowbase = blockIdx.y * 128;
    if (rowbase >= cnt) return;
    int off = d_off[e], ct = blockIdx.x;
    int tid = threadIdx.x, warp = tid >> 5, lane = tid & 31;
    int wm = (warp & 1) * 64, wn = (warp >> 1) * 32;

    int* sTok = (int*)smem;
    if (tid < 128) {
        int gr = rowbase + tid;
        sTok[tid] = (gr < cnt) ? (d_pair_slot[off + gr] >> 1) : -1;
    }
    __syncthreads();

    const __nv_bfloat16* wbH = d_w1hi + ((size_t)e * NI2 + (size_t)ct * 128) * H_DIM;
    const __nv_bfloat16* wbL = d_w1lo + ((size_t)e * NI2 + (size_t)ct * 128) * H_DIM;

    float acc[4][4][4];
#pragma unroll
    for (int mi = 0; mi < 4; mi++)
#pragma unroll
        for (int ni = 0; ni < 4; ni++)
#pragma unroll
            for (int j = 0; j < 4; j++) acc[mi][ni][j] = 0.f;

    const int NKB = H_DIM / 32;   // 64
    auto issue = [&](int kb) {
        char* st = smem + 512 + (size_t)(kb & 1) * STAGE_BYTES;
        int k0 = kb * 32;
#pragma unroll
        for (int i = 0; i < 8; i++) {
            int idx = tid + i * 256;
            int c = idx & 3, r = (idx >> 2) & 127, arr = idx >> 9;
            uint32_t sa = smem_u32(st + arr * ARR_BYTES + r * PITCHB + c * 16);
            const __nv_bfloat16* g; int sz = 16;
            if (arr < 2) {
                int tok = sTok[r];
                if (tok < 0) { tok = 0; sz = 0; }
                g = (arr == 0 ? d_xhi : d_xlo) + (size_t)tok * H_DIM + k0 + c * 8;
            } else {
                g = (arr == 2 ? wbH : wbL) + (size_t)r * H_DIM + k0 + c * 8;
            }
            cpa16(sa, g, sz);
        }
        asm volatile("cp.async.commit_group;");
    };

    issue(0);
    for (int kb = 0; kb < NKB; kb++) {
        if (kb + 1 < NKB) {
            issue(kb + 1);
            asm volatile("cp.async.wait_group 1;" ::: "memory");
        } else {
            asm volatile("cp.async.wait_group 0;" ::: "memory");
        }
        __syncthreads();
        char* st = smem + 512 + (size_t)(kb & 1) * STAGE_BYTES;
        char* pAh = st;
        char* pAl = st + ARR_BYTES;
        char* pBh = st + 2 * ARR_BYTES;
        char* pBl = st + 3 * ARR_BYTES;
        COMPUTE_SLAB(pAh, pAl, pBh, pBl);
        __syncthreads();
    }

    // epilogue: (c0,c1) = (gate, up) at same h column; (c2,c3) likewise at row+8
#pragma unroll
    for (int mi = 0; mi < 4; mi++) {
        int gr0 = rowbase + wm + mi * 16 + (lane >> 2);
        int gr1 = gr0 + 8;
#pragma unroll
        for (int ni = 0; ni < 4; ni++) {
            int ncol = wn + ni * 8 + (lane & 3) * 2;
            int hc = ct * 64 + (ncol >> 1);
            if (gr0 < cnt) {
                float g = acc[mi][ni][0], u = acc[mi][ni][1];
                float y = u * g / (1.f + __expf(-g));
                __nv_bfloat16 h, l; split_bf16(y, h, l);
                d_hhi[(size_t)(off + gr0) * I_DIM + hc] = h;
                d_hlo[(size_t)(off + gr0) * I_DIM + hc] = l;
            }
            if (gr1 < cnt) {
                float g = acc[mi][ni][2], u = acc[mi][ni][3];
                float y = u * g / (1.f + __expf(-g));
                __nv_bfloat16 h, l; split_bf16(y, h, l);
                d_hhi[(size_t)(off + gr1) * I_DIM + hc] = h;
                d_hlo[(size_t)(off + gr1) * I_DIM + hc] = l;
            }
        }
    }
}

// ---------------- GEMM2: h @ Wdown^T -> y ----------------
__global__ void __launch_bounds__(256, 2) k_gemm2() {
    extern __shared__ char smem[];
    int e = blockIdx.z;
    int cnt = d_count[e];
    int rowbase = blockIdx.y * 128;
    if (rowbase >= cnt) return;
    int off = d_off[e], nt = blockIdx.x;
    int tid = threadIdx.x, warp = tid >> 5, lane = tid & 31;
    int wm = (warp & 1) * 64, wn = (warp >> 1) * 32;

    const __nv_bfloat16* wbH = d_w2hi + ((size_t)e * H_DIM + (size_t)nt * 128) * I_DIM;
    const __nv_bfloat16* wbL = d_w2lo + ((size_t)e * H_DIM + (size_t)nt * 128) * I_DIM;
    const __nv_bfloat16* aH0 = d_hhi + (size_t)(off + rowbase) * I_DIM;
    const __nv_bfloat16* aL0 = d_hlo + (size_t)(off + rowbase) * I_DIM;

    float acc[4][4][4];
#pragma unroll
    for (int mi = 0; mi < 4; mi++)
#pragma unroll
        for (int ni = 0; ni < 4; ni++)
#pragma unroll
            for (int j = 0; j < 4; j++) acc[mi][ni][j] = 0.f;

    const int NKB = I_DIM / 32;   // 44
    auto issue = [&](int kb) {
        char* st = smem + 512 + (size_t)(kb & 1) * STAGE_BYTES;
        int k0 = kb * 32;
#pragma unroll
        for (int i = 0; i < 8; i++) {
            int idx = tid + i * 256;
            int c = idx & 3, r = (idx >> 2) & 127, arr = idx >> 9;
            uint32_t sa = smem_u32(st + arr * ARR_BYTES + r * PITCHB + c * 16);
            const __nv_bfloat16* g; int sz = 16;
            if (arr < 2) {
                if (rowbase + r >= cnt) sz = 0;
                g = (arr == 0 ? aH0 : aL0) + (size_t)r * I_DIM + k0 + c * 8;
            } else {
                g = (arr == 2 ? wbH : wbL) + (size_t)r * I_DIM + k0 + c * 8;
            }
            cpa16(sa, g, sz);
        }
        asm volatile("cp.async.commit_group;");
    };

    __syncthreads();
    issue(0);
    for (int kb = 0; kb < NKB; kb++) {
        if (kb + 1 < NKB) {
            issue(kb + 1);
            asm volatile("cp.async.wait_group 1;" ::: "memory");
        } else {
            asm volatile("cp.async.wait_group 0;" ::: "memory");
        }
        __syncthreads();
        char* st = smem + 512 + (size_t)(kb & 1) * STAGE_BYTES;
        char* pAh = st;
        char* pAl = st + ARR_BYTES;
        char* pBh = st + 2 * ARR_BYTES;
        char* pBl = st + 3 * ARR_BYTES;
        COMPUTE_SLAB(pAh, pAl, pBh, pBl);
        __syncthreads();
    }

#pragma unroll
    for (int mi = 0; mi < 4; mi++) {
        int gr0 = rowbase + wm + mi * 16 + (lane >> 2);
        int gr1 = gr0 + 8;
#pragma unroll
        for (int ni = 0; ni < 4; ni++) {
            int col = nt * 128 + wn + ni * 8 + (lane & 3) * 2;
            if (gr0 < cnt) {
                float2 v = make_float2(acc[mi][ni][0], acc[mi][ni][1]);
                *(float2*)&d_y[(size_t)(off + gr0) * H_DIM + col] = v;
            }
            if (gr1 < cnt) {
                float2 v = make_float2(acc[mi][ni][2], acc[mi][ni][3]);
                *(float2*)&d_y[(size_t)(off + gr1) * H_DIM + col] = v;
            }
        }
    }
}

// ---------------- combine: out = w0*y[p0] + w1*y[p1] (deterministic) ----------------
__global__ void k_combine(float* __restrict__ out) {
    size_t idx = (size_t)blockIdx.x * 256 + threadIdx.x;   // one float4 of out
    const int H4 = H_DIM / 4;
    int t = (int)(idx / H4);
    int c = (int)(idx % H4);
    int p0 = d_pos[2 * t], p1 = d_pos[2 * t + 1];
    float w0 = d_tok_w[2 * t], w1 = d_tok_w[2 * t + 1];
    const float4* y = (const float4*)d_y;
    float4 a = y[(size_t)p0 * H4 + c];
    float4 b = y[(size_t)p1 * H4 + c];
    float4 o;
    o.x = w0 * a.x + w1 * b.x;
    o.y = w0 * a.y + w1 * b.y;
    o.z = w0 * a.z + w1 * b.z;
    o.w = w0 * a.w + w1 * b.w;
    ((float4*)out)[idx] = o;
}

// ---------------- launch ----------------
extern "C" void kernel_launch(void* const* d_in, const int* in_sizes, int n_in,
                              void* d_out, int out_size) {
    const float* x  = (const float*)d_in[0];   // [T, H]
    const float* gw = (const float*)d_in[1];   // [E, H]
    const float* wg = (const float*)d_in[2];   // [E, H, I]
    const float* wu = (const float*)d_in[3];   // [E, H, I]
    const float* wd = (const float*)d_in[4];   // [E, I, H]
    float* out = (float*)d_out;                // [T, H]

    cudaFuncSetAttribute(k_gemm1, cudaFuncAttributeMaxDynamicSharedMemorySize, SMEM_DYN);
    cudaFuncSetAttribute(k_gemm2, cudaFuncAttributeMaxDynamicSharedMemorySize, SMEM_DYN);

    k_convx<<<(int)((size_t)T_TOK * H_DIM / 4 / 256), 256>>>(x);
    k_w1t<<<dim3(I_DIM / 32, H_DIM / 32, E_NUM * 2), dim3(32, 8)>>>(wg, wu);
    k_w2t<<<dim3(H_DIM / 32, I_DIM / 32, E_NUM), dim3(32, 8)>>>(wd);
    k_router<<<T_TOK / 8, 256>>>(x, gw);
    k_scan<<<1, 32>>>();
    k_fill<<<T_TOK / 256, 256>>>();
    k_gemm1<<<dim3(NI2 / 128, T_TOK / 128, E_NUM), 256, SMEM_DYN>>>();
    k_gemm2<<<dim3(H_DIM / 128, T_TOK / 128, E_NUM), 256, SMEM_DYN>>>();
    k_combine<<<(int)((size_t)T_TOK * H_DIM / 4 / 256), 256>>>(out);
}

// round 6
// speedup vs baseline: 1.7850x; 1.4265x over previous
#include <cuda_runtime.h>
#include <cuda_bf16.h>
#include <cuda_fp16.h>
#include <cstdint>

#define T_TOK 8192
#define H_DIM 2048
#define I_DIM 1408
#define E_NUM 8
#define NI2   (2 * I_DIM)   // 2816 interleaved gate/up columns
#define WSCALE 64.0f
#define WINV   (1.0f / 64.0f)

// ---------------- scratch (device globals; no allocations) ----------------
__device__ int   d_count[E_NUM];
__device__ int   d_cursor[E_NUM];
__device__ int   d_off[E_NUM];
__device__ int   d_tok_e[T_TOK * 2];
__device__ float d_tok_w[T_TOK * 2];
__device__ int   d_pos[T_TOK * 2];          // token,k -> compacted pair position
__device__ int   d_pair_slot[T_TOK * 2];    // compacted: tok*2+k

__device__ __align__(16) __half d_xh[(size_t)T_TOK * H_DIM];                 // x fp16
__device__ __align__(16) __half d_w1hi[(size_t)E_NUM * NI2 * H_DIM];         // W1*64 hi
__device__ __align__(16) __half d_w1lo[(size_t)E_NUM * NI2 * H_DIM];         // W1*64 lo
__device__ __align__(16) __half d_w2hi[(size_t)E_NUM * H_DIM * I_DIM];       // W2^T*64 hi
__device__ __align__(16) __half d_w2lo[(size_t)E_NUM * H_DIM * I_DIM];       // W2^T*64 lo
__device__ __align__(16) __half d_h[(size_t)T_TOK * 2 * I_DIM];              // activations fp16
__device__ __align__(16) float  d_y[(size_t)T_TOK * 2 * H_DIM];

// ---------------- helpers ----------------
static __device__ __forceinline__ uint32_t smem_u32(const void* p) {
    return (uint32_t)__cvta_generic_to_shared(p);
}
static __device__ __forceinline__ void ldsm4(uint32_t& r0, uint32_t& r1, uint32_t& r2, uint32_t& r3, uint32_t a) {
    asm volatile("ldmatrix.sync.aligned.m8n8.x4.shared.b16 {%0,%1,%2,%3},[%4];"
                 : "=r"(r0), "=r"(r1), "=r"(r2), "=r"(r3) : "r"(a));
}
static __device__ __forceinline__ void mma_fp16(float* c, const uint32_t* a, const uint32_t* b) {
    asm volatile("mma.sync.aligned.m16n8k16.row.col.f32.f16.f16.f32 "
                 "{%0,%1,%2,%3},{%4,%5,%6,%7},{%8,%9},{%0,%1,%2,%3};"
                 : "+f"(c[0]), "+f"(c[1]), "+f"(c[2]), "+f"(c[3])
                 : "r"(a[0]), "r"(a[1]), "r"(a[2]), "r"(a[3]), "r"(b[0]), "r"(b[1]));
}
static __device__ __forceinline__ void cpa16(uint32_t s, const void* g, int sz) {
    asm volatile("cp.async.cg.shared.global [%0], [%1], 16, %2;" :: "r"(s), "l"(g), "r"(sz));
}
static __device__ __forceinline__ void split_h16(float f, __half& hi, __half& lo) {
    hi = __float2half_rn(f);
    lo = __float2half_rn(f - __half2float(hi));
}

// smem geometry: 3 arrays per stage (A, Bh, Bl), each 128 rows x 32 halfs, 80B pitch
#define PITCHB      80
#define ARR_BYTES   (128 * PITCHB)            // 10240
#define STAGE_BYTES (3 * ARR_BYTES)           // 30720
#define N_STAGE     3
#define SMEM_DYN    (512 + N_STAGE * STAGE_BYTES)   // 92672

// ---------------- pre-pass: x -> fp16; zero counters ----------------
__global__ void k_convx(const float* __restrict__ x) {
    if (blockIdx.x == 0 && threadIdx.x < E_NUM) d_count[threadIdx.x] = 0;
    size_t idx = (size_t)blockIdx.x * 256 + threadIdx.x;        // one float4
    float4 v = ((const float4*)x)[idx];
    __half2 a = __floats2half2_rn(v.x, v.y);
    __half2 b = __floats2half2_rn(v.z, v.w);
    ((__half2*)d_xh)[2 * idx + 0] = a;
    ((__half2*)d_xh)[2 * idx + 1] = b;
}

// ---------------- pre-pass: W1 transpose+interleave -> [e][2i+mat][H], *64, fp16 hi/lo ----------------
__global__ void k_w1t(const float* __restrict__ wg, const float* __restrict__ wu) {
    __shared__ float tile[32][33];
    int mat = blockIdx.z & 1, e = blockIdx.z >> 1;
    const float* src = (mat ? wu : wg) + (size_t)e * H_DIM * I_DIM;
    int i0 = blockIdx.x * 32, h0 = blockIdx.y * 32;
    int tx = threadIdx.x, ty = threadIdx.y;
#pragma unroll
    for (int j = 0; j < 4; j++)
        tile[ty + 8 * j][tx] = src[(size_t)(h0 + ty + 8 * j) * I_DIM + i0 + tx];
    __syncthreads();
#pragma unroll
    for (int j = 0; j < 4; j++) {
        int oi = i0 + ty + 8 * j, oh = h0 + tx;
        float v = tile[tx][ty + 8 * j] * WSCALE;
        __half hb, lb; split_h16(v, hb, lb);
        size_t o = ((size_t)e * NI2 + 2 * oi + mat) * H_DIM + oh;
        d_w1hi[o] = hb; d_w1lo[o] = lb;
    }
}

// ---------------- pre-pass: Wdown transpose -> [e][h][i], *64, fp16 hi/lo ----------------
__global__ void k_w2t(const float* __restrict__ wd) {
    __shared__ float tile[32][33];
    int e = blockIdx.z;
    const float* src = wd + (size_t)e * I_DIM * H_DIM;
    int h0 = blockIdx.x * 32, i0 = blockIdx.y * 32;
    int tx = threadIdx.x, ty = threadIdx.y;
#pragma unroll
    for (int j = 0; j < 4; j++)
        tile[ty + 8 * j][tx] = src[(size_t)(i0 + ty + 8 * j) * H_DIM + h0 + tx];
    __syncthreads();
#pragma unroll
    for (int j = 0; j < 4; j++) {
        int oh = h0 + ty + 8 * j, oi = i0 + tx;
        float v = tile[tx][ty + 8 * j] * WSCALE;
        __half hb, lb; split_h16(v, hb, lb);
        size_t o = ((size_t)e * H_DIM + oh) * I_DIM + oi;
        d_w2hi[o] = hb; d_w2lo[o] = lb;
    }
}

// ---------------- router (warp per token, fp32 for exact top-k) ----------------
__global__ void k_router(const float* __restrict__ x, const float* __restrict__ gw) {
    int warp = (blockIdx.x * blockDim.x + threadIdx.x) >> 5;
    int lane = threadIdx.x & 31;
    if (warp >= T_TOK) return;
    const float* xr = x + (size_t)warp * H_DIM;
    float acc[E_NUM];
#pragma unroll
    for (int e = 0; e < E_NUM; e++) acc[e] = 0.f;
    for (int i = lane; i < H_DIM; i += 32) {
        float xv = xr[i];
#pragma unroll
        for (int e = 0; e < E_NUM; e++) acc[e] += xv * gw[e * H_DIM + i];
    }
#pragma unroll
    for (int e = 0; e < E_NUM; e++)
#pragma unroll
        for (int o = 16; o > 0; o >>= 1) acc[e] += __shfl_xor_sync(0xffffffffu, acc[e], o);
    if (lane == 0) {
        float m = acc[0];
#pragma unroll
        for (int e = 1; e < E_NUM; e++) m = fmaxf(m, acc[e]);
        float p[E_NUM];
#pragma unroll
        for (int e = 0; e < E_NUM; e++) p[e] = __expf(acc[e] - m);
        int e0 = 0; float w0 = p[0];
#pragma unroll
        for (int e = 1; e < E_NUM; e++) if (p[e] > w0) { w0 = p[e]; e0 = e; }
        int e1 = -1; float w1 = -1.f;
#pragma unroll
        for (int e = 0; e < E_NUM; e++) if (e != e0 && p[e] > w1) { w1 = p[e]; e1 = e; }
        float inv = 1.f / (w0 + w1);
        d_tok_e[warp * 2 + 0] = e0; d_tok_w[warp * 2 + 0] = w0 * inv;
        d_tok_e[warp * 2 + 1] = e1; d_tok_w[warp * 2 + 1] = w1 * inv;
        atomicAdd(&d_count[e0], 1);
        atomicAdd(&d_count[e1], 1);
    }
}

__global__ void k_scan() {
    if (threadIdx.x == 0) {
        int c = 0;
        for (int e = 0; e < E_NUM; e++) { d_off[e] = c; c += d_count[e]; d_cursor[e] = 0; }
    }
}

__global__ void k_fill() {
    int t = blockIdx.x * blockDim.x + threadIdx.x;
    if (t >= T_TOK) return;
#pragma unroll
    for (int k = 0; k < 2; k++) {
        int e = d_tok_e[t * 2 + k];
        int pos = atomicAdd(&d_cursor[e], 1);
        int p = d_off[e] + pos;
        d_pair_slot[p] = t * 2 + k;
        d_pos[t * 2 + k] = p;
    }
}

// ---------------- MMA over one 32-K smem stage (fp16 2-pass), warp tile 64x32 ----------------
// A array: [m][k] 80B pitch (single fp16); B arrays: [n][k] hi/lo. Non-trans ldmatrix.
#define COMPUTE_SLAB(pA, pBh, pBl)                                                      \
    _Pragma("unroll")                                                                   \
    for (int kk = 0; kk < 32; kk += 16) {                                               \
        uint32_t afr[4][4], bh[4][2], bl[4][2];                                         \
        _Pragma("unroll")                                                               \
        for (int p = 0; p < 2; p++) {                                                   \
            int bn = wn + p * 16 + ((lane >> 4) << 3) + (lane & 7);                     \
            int bk = kk + ((lane >> 3) & 1) * 8;                                        \
            uint32_t r0, r1, r2, r3;                                                    \
            ldsm4(r0, r1, r2, r3, smem_u32(pBh + bn * PITCHB + bk * 2));                \
            bh[p * 2][0] = r0; bh[p * 2][1] = r1;                                       \
            bh[p * 2 + 1][0] = r2; bh[p * 2 + 1][1] = r3;                               \
            ldsm4(r0, r1, r2, r3, smem_u32(pBl + bn * PITCHB + bk * 2));                \
            bl[p * 2][0] = r0; bl[p * 2][1] = r1;                                       \
            bl[p * 2 + 1][0] = r2; bl[p * 2 + 1][1] = r3;                               \
        }                                                                               \
        _Pragma("unroll")                                                               \
        for (int mi = 0; mi < 4; mi++) {                                                \
            int row = wm + mi * 16 + (lane & 15);                                       \
            int col = kk + (lane >> 4) * 8;                                             \
            ldsm4(afr[mi][0], afr[mi][1], afr[mi][2], afr[mi][3],                       \
                  smem_u32(pA + row * PITCHB + col * 2));                               \
        }                                                                               \
        _Pragma("unroll")                                                               \
        for (int mi = 0; mi < 4; mi++)                                                  \
            _Pragma("unroll")                                                           \
            for (int ni = 0; ni < 4; ni++) {                                            \
                mma_fp16(acc[mi][ni], afr[mi], bh[ni]);                                 \
                mma_fp16(acc[mi][ni], afr[mi], bl[ni]);                                 \
            }                                                                           \
    }

// ---------------- GEMM1: gathered X @ [Wgate ⧉ Wup]*64 -> h (SiLU*up) ----------------
__global__ void __launch_bounds__(256, 2) k_gemm1() {
    extern __shared__ char smem[];
    int e = blockIdx.z;
    int cnt = d_count[e];
    int rowbase = blockIdx.y * 128;
    if (rowbase >= cnt) return;
    int off = d_off[e], ct = blockIdx.x;
    int tid = threadIdx.x, warp = tid >> 5, lane = tid & 31;
    int wm = (warp & 1) * 64, wn = (warp >> 1) * 32;

    int* sTok = (int*)smem;
    if (tid < 128) {
        int gr = rowbase + tid;
        sTok[tid] = (gr < cnt) ? (d_pair_slot[off + gr] >> 1) : -1;
    }
    __syncthreads();

    const __half* wbH = d_w1hi + ((size_t)e * NI2 + (size_t)ct * 128) * H_DIM;
    const __half* wbL = d_w1lo + ((size_t)e * NI2 + (size_t)ct * 128) * H_DIM;

    float acc[4][4][4];
#pragma unroll
    for (int mi = 0; mi < 4; mi++)
#pragma unroll
        for (int ni = 0; ni < 4; ni++)
#pragma unroll
            for (int j = 0; j < 4; j++) acc[mi][ni][j] = 0.f;

    const int NKB = H_DIM / 32;   // 64
    auto issue = [&](int kb) {
        char* st = smem + 512 + (size_t)(kb % N_STAGE) * STAGE_BYTES;
        int k0 = kb * 32;
#pragma unroll
        for (int i = 0; i < 6; i++) {
            int idx = tid + i * 256;
            int c = idx & 3, r = (idx >> 2) & 127, arr = idx >> 9;
            uint32_t sa = smem_u32(st + arr * ARR_BYTES + r * PITCHB + c * 16);
            const __half* g; int sz = 16;
            if (arr == 0) {
                int tok = sTok[r];
                if (tok < 0) { tok = 0; sz = 0; }
                g = d_xh + (size_t)tok * H_DIM + k0 + c * 8;
            } else {
                g = (arr == 1 ? wbH : wbL) + (size_t)r * H_DIM + k0 + c * 8;
            }
            cpa16(sa, g, sz);
        }
        asm volatile("cp.async.commit_group;");
    };

    issue(0); issue(1);
    for (int kb = 0; kb < NKB; kb++) {
        if (kb + 2 < NKB) {
            issue(kb + 2);
            asm volatile("cp.async.wait_group 2;" ::: "memory");
        } else if (kb + 1 < NKB) {
            asm volatile("cp.async.wait_group 1;" ::: "memory");
        } else {
            asm volatile("cp.async.wait_group 0;" ::: "memory");
        }
        __syncthreads();
        char* st = smem + 512 + (size_t)(kb % N_STAGE) * STAGE_BYTES;
        char* pA  = st;
        char* pBh = st + ARR_BYTES;
        char* pBl = st + 2 * ARR_BYTES;
        COMPUTE_SLAB(pA, pBh, pBl);
        __syncthreads();
    }

    // epilogue: (c0,c1) = (gate, up)*64 at same h column; unscale BEFORE silu
#pragma unroll
    for (int mi = 0; mi < 4; mi++) {
        int gr0 = rowbase + wm + mi * 16 + (lane >> 2);
        int gr1 = gr0 + 8;
#pragma unroll
        for (int ni = 0; ni < 4; ni++) {
            int ncol = wn + ni * 8 + (lane & 3) * 2;
            int hc = ct * 64 + (ncol >> 1);
            if (gr0 < cnt) {
                float g = acc[mi][ni][0] * WINV, u = acc[mi][ni][1] * WINV;
                float y = u * g / (1.f + __expf(-g));
                d_h[(size_t)(off + gr0) * I_DIM + hc] = __float2half_rn(y);
            }
            if (gr1 < cnt) {
                float g = acc[mi][ni][2] * WINV, u = acc[mi][ni][3] * WINV;
                float y = u * g / (1.f + __expf(-g));
                d_h[(size_t)(off + gr1) * I_DIM + hc] = __float2half_rn(y);
            }
        }
    }
}

// ---------------- GEMM2: h @ (Wdown*64)^T -> y ----------------
__global__ void __launch_bounds__(256, 2) k_gemm2() {
    extern __shared__ char smem[];
    int e = blockIdx.z;
    int cnt = d_count[e];
    int rowbase = blockIdx.y * 128;
    if (rowbase >= cnt) return;
    int off = d_off[e], nt = blockIdx.x;
    int tid = threadIdx.x, warp = tid >> 5, lane = tid & 31;
    int wm = (warp & 1) * 64, wn = (warp >> 1) * 32;

    const __half* wbH = d_w2hi + ((size_t)e * H_DIM + (size_t)nt * 128) * I_DIM;
    const __half* wbL = d_w2lo + ((size_t)e * H_DIM + (size_t)nt * 128) * I_DIM;
    const __half* aH0 = d_h + (size_t)(off + rowbase) * I_DIM;

    float acc[4][4][4];
#pragma unroll
    for (int mi = 0; mi < 4; mi++)
#pragma unroll
        for (int ni = 0; ni < 4; ni++)
#pragma unroll
            for (int j = 0; j < 4; j++) acc[mi][ni][j] = 0.f;

    const int NKB = I_DIM / 32;   // 44
    auto issue = [&](int kb) {
        char* st = smem + 512 + (size_t)(kb % N_STAGE) * STAGE_BYTES;
        int k0 = kb * 32;
#pragma unroll
        for (int i = 0; i < 6; i++) {
            int idx = tid + i * 256;
            int c = idx & 3, r = (idx >> 2) & 127, arr = idx >> 9;
            uint32_t sa = smem_u32(st + arr * ARR_BYTES + r * PITCHB + c * 16);
            const __half* g; int sz = 16;
            if (arr == 0) {
                if (rowbase + r >= cnt) sz = 0;
                g = aH0 + (size_t)r * I_DIM + k0 + c * 8;
            } else {
                g = (arr == 1 ? wbH : wbL) + (size_t)r * I_DIM + k0 + c * 8;
            }
            cpa16(sa, g, sz);
        }
        asm volatile("cp.async.commit_group;");
    };

    __syncthreads();
    issue(0); issue(1);
    for (int kb = 0; kb < NKB; kb++) {
        if (kb + 2 < NKB) {
            issue(kb + 2);
            asm volatile("cp.async.wait_group 2;" ::: "memory");
        } else if (kb + 1 < NKB) {
            asm volatile("cp.async.wait_group 1;" ::: "memory");
        } else {
            asm volatile("cp.async.wait_group 0;" ::: "memory");
        }
        __syncthreads();
        char* st = smem + 512 + (size_t)(kb % N_STAGE) * STAGE_BYTES;
        char* pA  = st;
        char* pBh = st + ARR_BYTES;
        char* pBl = st + 2 * ARR_BYTES;
        COMPUTE_SLAB(pA, pBh, pBl);
        __syncthreads();
    }

#pragma unroll
    for (int mi = 0; mi < 4; mi++) {
        int gr0 = rowbase + wm + mi * 16 + (lane >> 2);
        int gr1 = gr0 + 8;
#pragma unroll
        for (int ni = 0; ni < 4; ni++) {
            int col = nt * 128 + wn + ni * 8 + (lane & 3) * 2;
            if (gr0 < cnt) {
                float2 v = make_float2(acc[mi][ni][0] * WINV, acc[mi][ni][1] * WINV);
                *(float2*)&d_y[(size_t)(off + gr0) * H_DIM + col] = v;
            }
            if (gr1 < cnt) {
                float2 v = make_float2(acc[mi][ni][2] * WINV, acc[mi][ni][3] * WINV);
                *(float2*)&d_y[(size_t)(off + gr1) * H_DIM + col] = v;
            }
        }
    }
}

// ---------------- combine: out = w0*y[p0] + w1*y[p1] (deterministic) ----------------
__global__ void k_combine(float* __restrict__ out) {
    size_t idx = (size_t)blockIdx.x * 256 + threadIdx.x;   // one float4 of out
    const int H4 = H_DIM / 4;
    int t = (int)(idx / H4);
    int c = (int)(idx % H4);
    int p0 = d_pos[2 * t], p1 = d_pos[2 * t + 1];
    float w0 = d_tok_w[2 * t], w1 = d_tok_w[2 * t + 1];
    const float4* y = (const float4*)d_y;
    float4 a = y[(size_t)p0 * H4 + c];
    float4 b = y[(size_t)p1 * H4 + c];
    float4 o;
    o.x = w0 * a.x + w1 * b.x;
    o.y = w0 * a.y + w1 * b.y;
    o.z = w0 * a.z + w1 * b.z;
    o.w = w0 * a.w + w1 * b.w;
    ((float4*)out)[idx] = o;
}

// ---------------- launch ----------------
extern "C" void kernel_launch(void* const* d_in, const int* in_sizes, int n_in,
                              void* d_out, int out_size) {
    const float* x  = (const float*)d_in[0];   // [T, H]
    const float* gw = (const float*)d_in[1];   // [E, H]
    const float* wg = (const float*)d_in[2];   // [E, H, I]
    const float* wu = (const float*)d_in[3];   // [E, H, I]
    const float* wd = (const float*)d_in[4];   // [E, I, H]
    float* out = (float*)d_out;                // [T, H]

    cudaFuncSetAttribute(k_gemm1, cudaFuncAttributeMaxDynamicSharedMemorySize, SMEM_DYN);
    cudaFuncSetAttribute(k_gemm2, cudaFuncAttributeMaxDynamicSharedMemorySize, SMEM_DYN);

    k_convx<<<(int)((size_t)T_TOK * H_DIM / 4 / 256), 256>>>(x);
    k_w1t<<<dim3(I_DIM / 32, H_DIM / 32, E_NUM * 2), dim3(32, 8)>>>(wg, wu);
    k_w2t<<<dim3(H_DIM / 32, I_DIM / 32, E_NUM), dim3(32, 8)>>>(wd);
    k_router<<<T_TOK / 8, 256>>>(x, gw);
    k_scan<<<1, 32>>>();
    k_fill<<<T_TOK / 256, 256>>>();
    k_gemm1<<<dim3(NI2 / 128, T_TOK / 128, E_NUM), 256, SMEM_DYN>>>();
    k_gemm2<<<dim3(H_DIM / 128, T_TOK / 128, E_NUM), 256, SMEM_DYN>>>();
    k_combine<<<(int)((size_t)T_TOK * H_DIM / 4 / 256), 256>>>(out);
}

// round 7
// speedup vs baseline: 1.8338x; 1.0273x over previous
#include <cuda_runtime.h>
#include <cuda_bf16.h>
#include <cuda_fp16.h>
#include <cstdint>

#define T_TOK 8192
#define H_DIM 2048
#define I_DIM 1408
#define E_NUM 8
#define NI2   (2 * I_DIM)   // 2816 interleaved gate/up columns
#define CAP   8192          // max rows per expert (top-2 of distinct experts)
#define WSCALE 64.0f
#define WINV   (1.0f / 64.0f)

// ---------------- scratch (device globals; no allocations) ----------------
__device__ int   d_count[E_NUM];                 // zero at load; re-zeroed by k_combine
__device__ float d_tok_w[T_TOK * 2];
__device__ int   d_pos[T_TOK * 2];               // token,k -> row in per-expert region
__device__ int   d_pair_slot[E_NUM * CAP];       // row -> tok*2+k

__device__ __align__(16) __half d_xh[(size_t)T_TOK * H_DIM];                 // x fp16
__device__ __align__(16) __half d_w1hi[(size_t)E_NUM * NI2 * H_DIM];         // W1*64 hi
__device__ __align__(16) __half d_w1lo[(size_t)E_NUM * NI2 * H_DIM];         // W1*64 lo
__device__ __align__(16) __half d_w2hi[(size_t)E_NUM * H_DIM * I_DIM];       // W2^T*64 hi
__device__ __align__(16) __half d_w2lo[(size_t)E_NUM * H_DIM * I_DIM];       // W2^T*64 lo
__device__ __align__(16) __half d_h[(size_t)E_NUM * CAP * I_DIM];            // activations fp16
__device__ __align__(16) float  d_y[(size_t)E_NUM * CAP * H_DIM];

// ---------------- helpers ----------------
static __device__ __forceinline__ uint32_t smem_u32(const void* p) {
    return (uint32_t)__cvta_generic_to_shared(p);
}
static __device__ __forceinline__ void ldsm4(uint32_t& r0, uint32_t& r1, uint32_t& r2, uint32_t& r3, uint32_t a) {
    asm volatile("ldmatrix.sync.aligned.m8n8.x4.shared.b16 {%0,%1,%2,%3},[%4];"
                 : "=r"(r0), "=r"(r1), "=r"(r2), "=r"(r3) : "r"(a));
}
static __device__ __forceinline__ void mma_fp16(float* c, const uint32_t* a, const uint32_t* b) {
    asm volatile("mma.sync.aligned.m16n8k16.row.col.f32.f16.f16.f32 "
                 "{%0,%1,%2,%3},{%4,%5,%6,%7},{%8,%9},{%0,%1,%2,%3};"
                 : "+f"(c[0]), "+f"(c[1]), "+f"(c[2]), "+f"(c[3])
                 : "r"(a[0]), "r"(a[1]), "r"(a[2]), "r"(a[3]), "r"(b[0]), "r"(b[1]));
}
static __device__ __forceinline__ void cpa16(uint32_t s, const void* g, int sz) {
    asm volatile("cp.async.cg.shared.global [%0], [%1], 16, %2;" :: "r"(s), "l"(g), "r"(sz));
}
static __device__ __forceinline__ void split_h16(float f, __half& hi, __half& lo) {
    hi = __float2half_rn(f);
    lo = __float2half_rn(f - __half2float(hi));
}

// smem geometry: 3 arrays per stage (A, Bh, Bl), each 128 rows x 32 halfs, 80B pitch
#define PITCHB      80
#define ARR_BYTES   (128 * PITCHB)            // 10240
#define STAGE_BYTES (3 * ARR_BYTES)           // 30720
#define N_STAGE     3
#define SMEM_DYN    (512 + N_STAGE * STAGE_BYTES)   // 92672

// ---------------- launch 1: router (fused compaction via per-expert capacity) ----------------
__global__ void k_router(const float* __restrict__ x, const float* __restrict__ gw) {
    int warp = (blockIdx.x * blockDim.x + threadIdx.x) >> 5;
    int lane = threadIdx.x & 31;
    if (warp >= T_TOK) return;
    const float* xr = x + (size_t)warp * H_DIM;
    float acc[E_NUM];
#pragma unroll
    for (int e = 0; e < E_NUM; e++) acc[e] = 0.f;
    for (int i = lane; i < H_DIM; i += 32) {
        float xv = xr[i];
#pragma unroll
        for (int e = 0; e < E_NUM; e++) acc[e] += xv * gw[e * H_DIM + i];
    }
#pragma unroll
    for (int e = 0; e < E_NUM; e++)
#pragma unroll
        for (int o = 16; o > 0; o >>= 1) acc[e] += __shfl_xor_sync(0xffffffffu, acc[e], o);
    if (lane == 0) {
        float m = acc[0];
#pragma unroll
        for (int e = 1; e < E_NUM; e++) m = fmaxf(m, acc[e]);
        float p[E_NUM];
#pragma unroll
        for (int e = 0; e < E_NUM; e++) p[e] = __expf(acc[e] - m);
        int e0 = 0; float w0 = p[0];
#pragma unroll
        for (int e = 1; e < E_NUM; e++) if (p[e] > w0) { w0 = p[e]; e0 = e; }
        int e1 = -1; float w1 = -1.f;
#pragma unroll
        for (int e = 0; e < E_NUM; e++) if (e != e0 && p[e] > w1) { w1 = p[e]; e1 = e; }
        float inv = 1.f / (w0 + w1);
        d_tok_w[warp * 2 + 0] = w0 * inv;
        d_tok_w[warp * 2 + 1] = w1 * inv;
        int p0 = e0 * CAP + atomicAdd(&d_count[e0], 1);
        int p1 = e1 * CAP + atomicAdd(&d_count[e1], 1);
        d_pair_slot[p0] = warp * 2 + 0;  d_pos[warp * 2 + 0] = p0;
        d_pair_slot[p1] = warp * 2 + 1;  d_pos[warp * 2 + 1] = p1;
    }
}

// ---------------- launch 2: x -> fp16 ----------------
__global__ void k_convx(const float* __restrict__ x) {
    size_t idx = (size_t)blockIdx.x * 256 + threadIdx.x;        // one float4
    float4 v = ((const float4*)x)[idx];
    ((__half2*)d_xh)[2 * idx + 0] = __floats2half2_rn(v.x, v.y);
    ((__half2*)d_xh)[2 * idx + 1] = __floats2half2_rn(v.z, v.w);
}

// ---------------- launch 3: W1 transpose+interleave -> [e][2i+mat][H], *64, fp16 hi/lo ----------------
__global__ void k_w1t(const float* __restrict__ wg, const float* __restrict__ wu) {
    __shared__ float tile[32][33];
    int mat = blockIdx.z & 1, e = blockIdx.z >> 1;
    const float* src = (mat ? wu : wg) + (size_t)e * H_DIM * I_DIM;
    int i0 = blockIdx.x * 32, h0 = blockIdx.y * 32;
    int tx = threadIdx.x, ty = threadIdx.y;
#pragma unroll
    for (int j = 0; j < 4; j++)
        tile[ty + 8 * j][tx] = src[(size_t)(h0 + ty + 8 * j) * I_DIM + i0 + tx];
    __syncthreads();
#pragma unroll
    for (int j = 0; j < 4; j++) {
        int oi = i0 + ty + 8 * j, oh = h0 + tx;
        float v = tile[tx][ty + 8 * j] * WSCALE;
        __half hb, lb; split_h16(v, hb, lb);
        size_t o = ((size_t)e * NI2 + 2 * oi + mat) * H_DIM + oh;
        d_w1hi[o] = hb; d_w1lo[o] = lb;
    }
}

// ---------------- launch 5: Wdown transpose -> [e][h][i], *64, fp16 hi/lo ----------------
__global__ void k_w2t(const float* __restrict__ wd) {
    __shared__ float tile[32][33];
    int e = blockIdx.z;
    const float* src = wd + (size_t)e * I_DIM * H_DIM;
    int h0 = blockIdx.x * 32, i0 = blockIdx.y * 32;
    int tx = threadIdx.x, ty = threadIdx.y;
#pragma unroll
    for (int j = 0; j < 4; j++)
        tile[ty + 8 * j][tx] = src[(size_t)(i0 + ty + 8 * j) * H_DIM + h0 + tx];
    __syncthreads();
#pragma unroll
    for (int j = 0; j < 4; j++) {
        int oh = h0 + ty + 8 * j, oi = i0 + tx;
        float v = tile[tx][ty + 8 * j] * WSCALE;
        __half hb, lb; split_h16(v, hb, lb);
        size_t o = ((size_t)e * H_DIM + oh) * I_DIM + oi;
        d_w2hi[o] = hb; d_w2lo[o] = lb;
    }
}

// ---------------- MMA over one 32-K smem stage (fp16 2-pass), warp tile 64x32 ----------------
#define COMPUTE_SLAB(pA, pBh, pBl)                                                      \
    _Pragma("unroll")                                                                   \
    for (int kk = 0; kk < 32; kk += 16) {                                               \
        uint32_t afr[4][4], bh[4][2], bl[4][2];                                         \
        _Pragma("unroll")                                                               \
        for (int p = 0; p < 2; p++) {                                                   \
            int bn = wn + p * 16 + ((lane >> 4) << 3) + (lane & 7);                     \
            int bk = kk + ((lane >> 3) & 1) * 8;                                        \
            uint32_t r0, r1, r2, r3;                                                    \
            ldsm4(r0, r1, r2, r3, smem_u32(pBh + bn * PITCHB + bk * 2));                \
            bh[p * 2][0] = r0; bh[p * 2][1] = r1;                                       \
            bh[p * 2 + 1][0] = r2; bh[p * 2 + 1][1] = r3;                               \
            ldsm4(r0, r1, r2, r3, smem_u32(pBl + bn * PITCHB + bk * 2));                \
            bl[p * 2][0] = r0; bl[p * 2][1] = r1;                                       \
            bl[p * 2 + 1][0] = r2; bl[p * 2 + 1][1] = r3;                               \
        }                                                                               \
        _Pragma("unroll")                                                               \
        for (int mi = 0; mi < 4; mi++) {                                                \
            int row = wm + mi * 16 + (lane & 15);                                       \
            int col = kk + (lane >> 4) * 8;                                             \
            ldsm4(afr[mi][0], afr[mi][1], afr[mi][2], afr[mi][3],                       \
                  smem_u32(pA + row * PITCHB + col * 2));                               \
        }                                                                               \
        _Pragma("unroll")                                                               \
        for (int mi = 0; mi < 4; mi++)                                                  \
            _Pragma("unroll")                                                           \
            for (int ni = 0; ni < 4; ni++) {                                            \
                mma_fp16(acc[mi][ni], afr[mi], bh[ni]);                                 \
                mma_fp16(acc[mi][ni], afr[mi], bl[ni]);                                 \
            }                                                                           \
    }

// ---------------- launch 4 (PROFILED): GEMM1 gathered X @ [Wgate ⧉ Wup]*64 -> h ----------------
__global__ void __launch_bounds__(256, 2) k_gemm1() {
    extern __shared__ char smem[];
    int e = blockIdx.z;
    int cnt = d_count[e];
    int rowbase = blockIdx.y * 128;
    if (rowbase >= cnt) return;
    int off = e * CAP, ct = blockIdx.x;
    int tid = threadIdx.x, warp = tid >> 5, lane = tid & 31;
    int wm = (warp & 1) * 64, wn = (warp >> 1) * 32;

    int* sTok = (int*)smem;
    if (tid < 128) {
        int gr = rowbase + tid;
        sTok[tid] = (gr < cnt) ? (d_pair_slot[off + gr] >> 1) : -1;
    }
    __syncthreads();

    const __half* wbH = d_w1hi + ((size_t)e * NI2 + (size_t)ct * 128) * H_DIM;
    const __half* wbL = d_w1lo + ((size_t)e * NI2 + (size_t)ct * 128) * H_DIM;

    float acc[4][4][4];
#pragma unroll
    for (int mi = 0; mi < 4; mi++)
#pragma unroll
        for (int ni = 0; ni < 4; ni++)
#pragma unroll
            for (int j = 0; j < 4; j++) acc[mi][ni][j] = 0.f;

    const int NKB = H_DIM / 32;   // 64
    auto issue = [&](int kb) {
        char* st = smem + 512 + (size_t)(kb % N_STAGE) * STAGE_BYTES;
        int k0 = kb * 32;
#pragma unroll
        for (int i = 0; i < 6; i++) {
            int idx = tid + i * 256;
            int c = idx & 3, r = (idx >> 2) & 127, arr = idx >> 9;
            uint32_t sa = smem_u32(st + arr * ARR_BYTES + r * PITCHB + c * 16);
            const __half* g; int sz = 16;
            if (arr == 0) {
                int tok = sTok[r];
                if (tok < 0) { tok = 0; sz = 0; }
                g = d_xh + (size_t)tok * H_DIM + k0 + c * 8;
            } else {
                g = (arr == 1 ? wbH : wbL) + (size_t)r * H_DIM + k0 + c * 8;
            }
            cpa16(sa, g, sz);
        }
        asm volatile("cp.async.commit_group;");
    };

    issue(0); issue(1);
    for (int kb = 0; kb < NKB; kb++) {
        if (kb + 1 < NKB) asm volatile("cp.async.wait_group 1;" ::: "memory");
        else              asm volatile("cp.async.wait_group 0;" ::: "memory");
        __syncthreads();
        if (kb + 2 < NKB) issue(kb + 2);
        char* st = smem + 512 + (size_t)(kb % N_STAGE) * STAGE_BYTES;
        char* pA  = st;
        char* pBh = st + ARR_BYTES;
        char* pBl = st + 2 * ARR_BYTES;
        COMPUTE_SLAB(pA, pBh, pBl);
    }

    // epilogue: (c0,c1) = (gate, up)*64 at same h column; unscale BEFORE silu
#pragma unroll
    for (int mi = 0; mi < 4; mi++) {
        int gr0 = rowbase + wm + mi * 16 + (lane >> 2);
        int gr1 = gr0 + 8;
#pragma unroll
        for (int ni = 0; ni < 4; ni++) {
            int ncol = wn + ni * 8 + (lane & 3) * 2;
            int hc = ct * 64 + (ncol >> 1);
            if (gr0 < cnt) {
                float g = acc[mi][ni][0] * WINV, u = acc[mi][ni][1] * WINV;
                float y = u * g / (1.f + __expf(-g));
                d_h[(size_t)(off + gr0) * I_DIM + hc] = __float2half_rn(y);
            }
            if (gr1 < cnt) {
                float g = acc[mi][ni][2] * WINV, u = acc[mi][ni][3] * WINV;
                float y = u * g / (1.f + __expf(-g));
                d_h[(size_t)(off + gr1) * I_DIM + hc] = __float2half_rn(y);
            }
        }
    }
}

// ---------------- launch 6: GEMM2 h @ (Wdown*64)^T -> y ----------------
__global__ void __launch_bounds__(256, 2) k_gemm2() {
    extern __shared__ char smem[];
    int e = blockIdx.z;
    int cnt = d_count[e];
    int rowbase = blockIdx.y * 128;
    if (rowbase >= cnt) return;
    int off = e * CAP, nt = blockIdx.x;
    int tid = threadIdx.x, warp = tid >> 5, lane = tid & 31;
    int wm = (warp & 1) * 64, wn = (warp >> 1) * 32;

    const __half* wbH = d_w2hi + ((size_t)e * H_DIM + (size_t)nt * 128) * I_DIM;
    const __half* wbL = d_w2lo + ((size_t)e * H_DIM + (size_t)nt * 128) * I_DIM;
    const __half* aH0 = d_h + (size_t)(off + rowbase) * I_DIM;

    float acc[4][4][4];
#pragma unroll
    for (int mi = 0; mi < 4; mi++)
#pragma unroll
        for (int ni = 0; ni < 4; ni++)
#pragma unroll
            for (int j = 0; j < 4; j++) acc[mi][ni][j] = 0.f;

    const int NKB = I_DIM / 32;   // 44
    auto issue = [&](int kb) {
        char* st = smem + 512 + (size_t)(kb % N_STAGE) * STAGE_BYTES;
        int k0 = kb * 32;
#pragma unroll
        for (int i = 0; i < 6; i++) {
            int idx = tid + i * 256;
            int c = idx & 3, r = (idx >> 2) & 127, arr = idx >> 9;
            uint32_t sa = smem_u32(st + arr * ARR_BYTES + r * PITCHB + c * 16);
            const __half* g; int sz = 16;
            if (arr == 0) {
                if (rowbase + r >= cnt) sz = 0;
                g = aH0 + (size_t)r * I_DIM + k0 + c * 8;
            } else {
                g = (arr == 1 ? wbH : wbL) + (size_t)r * I_DIM + k0 + c * 8;
            }
            cpa16(sa, g, sz);
        }
        asm volatile("cp.async.commit_group;");
    };

    issue(0); issue(1);
    for (int kb = 0; kb < NKB; kb++) {
        if (kb + 1 < NKB) asm volatile("cp.async.wait_group 1;" ::: "memory");
        else              asm volatile("cp.async.wait_group 0;" ::: "memory");
        __syncthreads();
        if (kb + 2 < NKB) issue(kb + 2);
        char* st = smem + 512 + (size_t)(kb % N_STAGE) * STAGE_BYTES;
        char* pA  = st;
        char* pBh = st + ARR_BYTES;
        char* pBl = st + 2 * ARR_BYTES;
        COMPUTE_SLAB(pA, pBh, pBl);
    }

#pragma unroll
    for (int mi = 0; mi < 4; mi++) {
        int gr0 = rowbase + wm + mi * 16 + (lane >> 2);
        int gr1 = gr0 + 8;
#pragma unroll
        for (int ni = 0; ni < 4; ni++) {
            int col = nt * 128 + wn + ni * 8 + (lane & 3) * 2;
            if (gr0 < cnt) {
                float2 v = make_float2(acc[mi][ni][0] * WINV, acc[mi][ni][1] * WINV);
                *(float2*)&d_y[(size_t)(off + gr0) * H_DIM + col] = v;
            }
            if (gr1 < cnt) {
                float2 v = make_float2(acc[mi][ni][2] * WINV, acc[mi][ni][3] * WINV);
                *(float2*)&d_y[(size_t)(off + gr1) * H_DIM + col] = v;
            }
        }
    }
}

// ---------------- launch 7: combine + re-zero counters for next replay ----------------
__global__ void k_combine(float* __restrict__ out) {
    if (blockIdx.x == 0 && threadIdx.x < E_NUM) d_count[threadIdx.x] = 0;
    size_t idx = (size_t)blockIdx.x * 256 + threadIdx.x;   // one float4 of out
    const int H4 = H_DIM / 4;
    int t = (int)(idx / H4);
    int c = (int)(idx % H4);
    int p0 = d_pos[2 * t], p1 = d_pos[2 * t + 1];
    float w0 = d_tok_w[2 * t], w1 = d_tok_w[2 * t + 1];
    const float4* y = (const float4*)d_y;
    float4 a = y[(size_t)p0 * H4 + c];
    float4 b = y[(size_t)p1 * H4 + c];
    float4 o;
    o.x = w0 * a.x + w1 * b.x;
    o.y = w0 * a.y + w1 * b.y;
    o.z = w0 * a.z + w1 * b.z;
    o.w = w0 * a.w + w1 * b.w;
    ((float4*)out)[idx] = o;
}

// ---------------- launch ----------------
extern "C" void kernel_launch(void* const* d_in, const int* in_sizes, int n_in,
                              void* d_out, int out_size) {
    const float* x  = (const float*)d_in[0];   // [T, H]
    const float* gw = (const float*)d_in[1];   // [E, H]
    const float* wg = (const float*)d_in[2];   // [E, H, I]
    const float* wu = (const float*)d_in[3];   // [E, H, I]
    const float* wd = (const float*)d_in[4];   // [E, I, H]
    float* out = (float*)d_out;                // [T, H]

    cudaFuncSetAttribute(k_gemm1, cudaFuncAttributeMaxDynamicSharedMemorySize, SMEM_DYN);
    cudaFuncSetAttribute(k_gemm2, cudaFuncAttributeMaxDynamicSharedMemorySize, SMEM_DYN);

    k_router<<<T_TOK / 8, 256>>>(x, gw);                                   // 1
    k_convx<<<(int)((size_t)T_TOK * H_DIM / 4 / 256), 256>>>(x);           // 2
    k_w1t<<<dim3(I_DIM / 32, H_DIM / 32, E_NUM * 2), dim3(32, 8)>>>(wg, wu); // 3
    k_gemm1<<<dim3(NI2 / 128, CAP / 128, E_NUM), 256, SMEM_DYN>>>();       // 4 <- profiled
    k_w2t<<<dim3(H_DIM / 32, I_DIM / 32, E_NUM), dim3(32, 8)>>>(wd);       // 5
    k_gemm2<<<dim3(H_DIM / 128, CAP / 128, E_NUM), 256, SMEM_DYN>>>();     // 6
    k_combine<<<(int)((size_t)T_TOK * H_DIM / 4 / 256), 256>>>(out);       // 7
}

// round 9
// speedup vs baseline: 2.1572x; 1.1763x over previous
#include <cuda_runtime.h>
#include <cuda_bf16.h>
#include <cuda_fp16.h>
#include <cstdint>

#define T_TOK 8192
#define H_DIM 2048
#define I_DIM 1408
#define E_NUM 8
#define NI2   (2 * I_DIM)   // 2816 interleaved gate/up columns
#define CAP   8192          // max rows per expert (top-2 of distinct experts)
#define WSCALE 64.0f
#define WINV   (1.0f / 64.0f)

// ---------------- scratch (device globals; no allocations) ----------------
__device__ int   d_count[E_NUM];                 // zero at load; re-zeroed by k_combine
__device__ float d_tok_w[T_TOK * 2];
__device__ int   d_pos[T_TOK * 2];               // token,k -> row in per-expert region
__device__ int   d_pair_slot[E_NUM * CAP];       // row -> tok*2+k

__device__ __align__(16) __half d_xh[(size_t)T_TOK * H_DIM];                 // x fp16
__device__ __align__(16) __half d_w1hi[(size_t)E_NUM * NI2 * H_DIM];         // W1*64 hi
__device__ __align__(16) __half d_w1lo[(size_t)E_NUM * NI2 * H_DIM];         // W1*64 lo
__device__ __align__(16) __half d_w2hi[(size_t)E_NUM * H_DIM * I_DIM];       // W2^T*64 hi (single-pass)
__device__ __align__(16) __half d_h[(size_t)E_NUM * CAP * I_DIM];            // activations fp16
__device__ __align__(16) float  d_y[(size_t)E_NUM * CAP * H_DIM];

// ---------------- helpers ----------------
static __device__ __forceinline__ uint32_t smem_u32(const void* p) {
    return (uint32_t)__cvta_generic_to_shared(p);
}
static __device__ __forceinline__ void ldsm4(uint32_t& r0, uint32_t& r1, uint32_t& r2, uint32_t& r3, uint32_t a) {
    asm volatile("ldmatrix.sync.aligned.m8n8.x4.shared.b16 {%0,%1,%2,%3},[%4];"
                 : "=r"(r0), "=r"(r1), "=r"(r2), "=r"(r3) : "r"(a));
}
static __device__ __forceinline__ void mma_fp16(float* c, const uint32_t* a, const uint32_t* b) {
    asm volatile("mma.sync.aligned.m16n8k16.row.col.f32.f16.f16.f32 "
                 "{%0,%1,%2,%3},{%4,%5,%6,%7},{%8,%9},{%0,%1,%2,%3};"
                 : "+f"(c[0]), "+f"(c[1]), "+f"(c[2]), "+f"(c[3])
                 : "r"(a[0]), "r"(a[1]), "r"(a[2]), "r"(a[3]), "r"(b[0]), "r"(b[1]));
}
static __device__ __forceinline__ void cpa16(uint32_t s, const void* g, int sz) {
    asm volatile("cp.async.cg.shared.global [%0], [%1], 16, %2;" :: "r"(s), "l"(g), "r"(sz));
}
static __device__ __forceinline__ void split_h16(float f, __half& hi, __half& lo) {
    hi = __float2half_rn(f);
    lo = __float2half_rn(f - __half2float(hi));
}

// GEMM1 smem geometry: 3 arrays per stage (A, Bh, Bl), each 128 rows x 32 halfs, 80B pitch
#define PITCHB      80
#define ARR_BYTES   (128 * PITCHB)            // 10240
#define STAGE_BYTES (3 * ARR_BYTES)           // 30720
#define N_STAGE     3
#define SMEM_DYN    (512 + N_STAGE * STAGE_BYTES)   // 92672

// GEMM2 smem geometry: 2 arrays per stage (A, B), each 128 rows x 64 halfs, 144B pitch
#define PITCH2      144
#define ARR2_BYTES  (128 * PITCH2)            // 18432
#define STAGE2      (2 * ARR2_BYTES)          // 36864
#define SMEM2       (512 + 2 * STAGE2)        // 74240

// ---------------- launch 1: router (fused compaction via per-expert capacity) ----------------
__global__ void k_router(const float* __restrict__ x, const float* __restrict__ gw) {
    int warp = (blockIdx.x * blockDim.x + threadIdx.x) >> 5;
    int lane = threadIdx.x & 31;
    if (warp >= T_TOK) return;
    const float* xr = x + (size_t)warp * H_DIM;
    float acc[E_NUM];
#pragma unroll
    for (int e = 0; e < E_NUM; e++) acc[e] = 0.f;
    for (int i = lane; i < H_DIM; i += 32) {
        float xv = xr[i];
#pragma unroll
        for (int e = 0; e < E_NUM; e++) acc[e] += xv * gw[e * H_DIM + i];
    }
#pragma unroll
    for (int e = 0; e < E_NUM; e++)
#pragma unroll
        for (int o = 16; o > 0; o >>= 1) acc[e] += __shfl_xor_sync(0xffffffffu, acc[e], o);
    if (lane == 0) {
        float m = acc[0];
#pragma unroll
        for (int e = 1; e < E_NUM; e++) m = fmaxf(m, acc[e]);
        float p[E_NUM];
#pragma unroll
        for (int e = 0; e < E_NUM; e++) p[e] = __expf(acc[e] - m);
        int e0 = 0; float w0 = p[0];
#pragma unroll
        for (int e = 1; e < E_NUM; e++) if (p[e] > w0) { w0 = p[e]; e0 = e; }
        int e1 = -1; float w1 = -1.f;
#pragma unroll
        for (int e = 0; e < E_NUM; e++) if (e != e0 && p[e] > w1) { w1 = p[e]; e1 = e; }
        float inv = 1.f / (w0 + w1);
        d_tok_w[warp * 2 + 0] = w0 * inv;
        d_tok_w[warp * 2 + 1] = w1 * inv;
        int p0 = e0 * CAP + atomicAdd(&d_count[e0], 1);
        int p1 = e1 * CAP + atomicAdd(&d_count[e1], 1);
        d_pair_slot[p0] = warp * 2 + 0;  d_pos[warp * 2 + 0] = p0;
        d_pair_slot[p1] = warp * 2 + 1;  d_pos[warp * 2 + 1] = p1;
    }
}

// ---------------- launch 2: x -> fp16 ----------------
__global__ void k_convx(const float* __restrict__ x) {
    size_t idx = (size_t)blockIdx.x * 256 + threadIdx.x;        // one float4
    float4 v = ((const float4*)x)[idx];
    ((__half2*)d_xh)[2 * idx + 0] = __floats2half2_rn(v.x, v.y);
    ((__half2*)d_xh)[2 * idx + 1] = __floats2half2_rn(v.z, v.w);
}

// ---------------- launch 3: W1 transpose+interleave -> [e][2i+mat][H], *64, fp16 hi/lo ----------------
__global__ void k_w1t(const float* __restrict__ wg, const float* __restrict__ wu) {
    __shared__ float tile[32][33];
    int mat = blockIdx.z & 1, e = blockIdx.z >> 1;
    const float* src = (mat ? wu : wg) + (size_t)e * H_DIM * I_DIM;
    int i0 = blockIdx.x * 32, h0 = blockIdx.y * 32;
    int tx = threadIdx.x, ty = threadIdx.y;
#pragma unroll
    for (int j = 0; j < 4; j++)
        tile[ty + 8 * j][tx] = src[(size_t)(h0 + ty + 8 * j) * I_DIM + i0 + tx];
    __syncthreads();
#pragma unroll
    for (int j = 0; j < 4; j++) {
        int oi = i0 + ty + 8 * j, oh = h0 + tx;
        float v = tile[tx][ty + 8 * j] * WSCALE;
        __half hb, lb; split_h16(v, hb, lb);
        size_t o = ((size_t)e * NI2 + 2 * oi + mat) * H_DIM + oh;
        d_w1hi[o] = hb; d_w1lo[o] = lb;
    }
}

// ---------------- launch 5: Wdown transpose -> [e][h][i], *64, fp16 hi only ----------------
__global__ void k_w2t(const float* __restrict__ wd) {
    __shared__ float tile[32][33];
    int e = blockIdx.z;
    const float* src = wd + (size_t)e * I_DIM * H_DIM;
    int h0 = blockIdx.x * 32, i0 = blockIdx.y * 32;
    int tx = threadIdx.x, ty = threadIdx.y;
#pragma unroll
    for (int j = 0; j < 4; j++)
        tile[ty + 8 * j][tx] = src[(size_t)(i0 + ty + 8 * j) * H_DIM + h0 + tx];
    __syncthreads();
#pragma unroll
    for (int j = 0; j < 4; j++) {
        int oh = h0 + ty + 8 * j, oi = i0 + tx;
        float v = tile[tx][ty + 8 * j] * WSCALE;
        size_t o = ((size_t)e * H_DIM + oh) * I_DIM + oi;
        d_w2hi[o] = __float2half_rn(v);
    }
}

// ---------------- MMA over one 32-K smem stage (fp16 2-pass B), warp tile 64x32 ----------------
#define COMPUTE_SLAB(pA, pBh, pBl)                                                      \
    _Pragma("unroll")                                                                   \
    for (int kk = 0; kk < 32; kk += 16) {                                               \
        uint32_t afr[4][4], bh[4][2], bl[4][2];                                         \
        _Pragma("unroll")                                                               \
        for (int p = 0; p < 2; p++) {                                                   \
            int bn = wn + p * 16 + ((lane >> 4) << 3) + (lane & 7);                     \
            int bk = kk + ((lane >> 3) & 1) * 8;                                        \
            uint32_t r0, r1, r2, r3;                                                    \
            ldsm4(r0, r1, r2, r3, smem_u32(pBh + bn * PITCHB + bk * 2));                \
            bh[p * 2][0] = r0; bh[p * 2][1] = r1;                                       \
            bh[p * 2 + 1][0] = r2; bh[p * 2 + 1][1] = r3;                               \
            ldsm4(r0, r1, r2, r3, smem_u32(pBl + bn * PITCHB + bk * 2));                \
            bl[p * 2][0] = r0; bl[p * 2][1] = r1;                                       \
            bl[p * 2 + 1][0] = r2; bl[p * 2 + 1][1] = r3;                               \
        }                                                                               \
        _Pragma("unroll")                                                               \
        for (int mi = 0; mi < 4; mi++) {                                                \
            int row = wm + mi * 16 + (lane & 15);                                       \
            int col = kk + (lane >> 4) * 8;                                             \
            ldsm4(afr[mi][0], afr[mi][1], afr[mi][2], afr[mi][3],                       \
                  smem_u32(pA + row * PITCHB + col * 2));                               \
        }                                                                               \
        _Pragma("unroll")                                                               \
        for (int mi = 0; mi < 4; mi++)                                                  \
            _Pragma("unroll")                                                           \
            for (int ni = 0; ni < 4; ni++) {                                            \
                mma_fp16(acc[mi][ni], afr[mi], bh[ni]);                                 \
                mma_fp16(acc[mi][ni], afr[mi], bl[ni]);                                 \
            }                                                                           \
    }

// ---------------- launch 4 (PROFILED): GEMM1 gathered X @ [Wgate ⧉ Wup]*64 -> h ----------------
__global__ void __launch_bounds__(256, 2) k_gemm1() {
    extern __shared__ char smem[];
    int e = blockIdx.z;
    int cnt = d_count[e];
    int rowbase = blockIdx.y * 128;
    if (rowbase >= cnt) return;
    int off = e * CAP, ct = blockIdx.x;
    int tid = threadIdx.x, warp = tid >> 5, lane = tid & 31;
    int wm = (warp & 1) * 64, wn = (warp >> 1) * 32;

    int* sTok = (int*)smem;
    if (tid < 128) {
        int gr = rowbase + tid;
        sTok[tid] = (gr < cnt) ? (d_pair_slot[off + gr] >> 1) : -1;
    }
    __syncthreads();

    const __half* wbH = d_w1hi + ((size_t)e * NI2 + (size_t)ct * 128) * H_DIM;
    const __half* wbL = d_w1lo + ((size_t)e * NI2 + (size_t)ct * 128) * H_DIM;

    float acc[4][4][4];
#pragma unroll
    for (int mi = 0; mi < 4; mi++)
#pragma unroll
        for (int ni = 0; ni < 4; ni++)
#pragma unroll
            for (int j = 0; j < 4; j++) acc[mi][ni][j] = 0.f;

    const int NKB = H_DIM / 32;   // 64
    auto issue = [&](int kb) {
        char* st = smem + 512 + (size_t)(kb % N_STAGE) * STAGE_BYTES;
        int k0 = kb * 32;
#pragma unroll
        for (int i = 0; i < 6; i++) {
            int idx = tid + i * 256;
            int c = idx & 3, r = (idx >> 2) & 127, arr = idx >> 9;
            uint32_t sa = smem_u32(st + arr * ARR_BYTES + r * PITCHB + c * 16);
            const __half* g; int sz = 16;
            if (arr == 0) {
                int tok = sTok[r];
                if (tok < 0) { tok = 0; sz = 0; }
                g = d_xh + (size_t)tok * H_DIM + k0 + c * 8;
            } else {
                g = (arr == 1 ? wbH : wbL) + (size_t)r * H_DIM + k0 + c * 8;
            }
            cpa16(sa, g, sz);
        }
        asm volatile("cp.async.commit_group;");
    };

    issue(0); issue(1);
    for (int kb = 0; kb < NKB; kb++) {
        if (kb + 1 < NKB) asm volatile("cp.async.wait_group 1;" ::: "memory");
        else              asm volatile("cp.async.wait_group 0;" ::: "memory");
        __syncthreads();
        if (kb + 2 < NKB) issue(kb + 2);
        char* st = smem + 512 + (size_t)(kb % N_STAGE) * STAGE_BYTES;
        char* pA  = st;
        char* pBh = st + ARR_BYTES;
        char* pBl = st + 2 * ARR_BYTES;
        COMPUTE_SLAB(pA, pBh, pBl);
    }

    // epilogue: (c0,c1) = (gate, up)*64 at same h column; unscale BEFORE silu
#pragma unroll
    for (int mi = 0; mi < 4; mi++) {
        int gr0 = rowbase + wm + mi * 16 + (lane >> 2);
        int gr1 = gr0 + 8;
#pragma unroll
        for (int ni = 0; ni < 4; ni++) {
            int ncol = wn + ni * 8 + (lane & 3) * 2;
            int hc = ct * 64 + (ncol >> 1);
            if (gr0 < cnt) {
                float g = acc[mi][ni][0] * WINV, u = acc[mi][ni][1] * WINV;
                float y = u * g / (1.f + __expf(-g));
                d_h[(size_t)(off + gr0) * I_DIM + hc] = __float2half_rn(y);
            }
            if (gr1 < cnt) {
                float g = acc[mi][ni][2] * WINV, u = acc[mi][ni][3] * WINV;
                float y = u * g / (1.f + __expf(-g));
                d_h[(size_t)(off + gr1) * I_DIM + hc] = __float2half_rn(y);
            }
        }
    }
}

// ---------------- launch 6: GEMM2 h @ (Wdown*64)^T -> y (single-pass, 64-K slabs) ----------------
__global__ void __launch_bounds__(256, 2) k_gemm2() {
    extern __shared__ char smem[];
    int e = blockIdx.z;
    int cnt = d_count[e];
    int rowbase = blockIdx.y * 128;
    if (rowbase >= cnt) return;
    int off = e * CAP, nt = blockIdx.x;
    int tid = threadIdx.x, warp = tid >> 5, lane = tid & 31;
    int wm = (warp & 1) * 64, wn = (warp >> 1) * 32;

    const __half* wbH = d_w2hi + ((size_t)e * H_DIM + (size_t)nt * 128) * I_DIM;
    const __half* aH0 = d_h + (size_t)(off + rowbase) * I_DIM;

    float acc[4][4][4];
#pragma unroll
    for (int mi = 0; mi < 4; mi++)
#pragma unroll
        for (int ni = 0; ni < 4; ni++)
#pragma unroll
            for (int j = 0; j < 4; j++) acc[mi][ni][j] = 0.f;

    const int NKB = I_DIM / 64;   // 22
    auto issue = [&](int kb) {
        char* st = smem + 512 + (size_t)(kb & 1) * STAGE2;
        int k0 = kb * 64;
#pragma unroll
        for (int i = 0; i < 8; i++) {
            int idx = tid + i * 256;
            int c = idx & 7, r = (idx >> 3) & 127, arr = idx >> 10;
            uint32_t sa = smem_u32(st + arr * ARR2_BYTES + r * PITCH2 + c * 16);
            const __half* g; int sz = 16;
            if (arr == 0) {
                if (rowbase + r >= cnt) sz = 0;
                g = aH0 + (size_t)r * I_DIM + k0 + c * 8;
            } else {
                g = wbH + (size_t)r * I_DIM + k0 + c * 8;
            }
            cpa16(sa, g, sz);
        }
        asm volatile("cp.async.commit_group;");
    };

    issue(0);
    for (int kb = 0; kb < NKB; kb++) {
        asm volatile("cp.async.wait_group 0;" ::: "memory");
        __syncthreads();
        if (kb + 1 < NKB) issue(kb + 1);
        char* st = smem + 512 + (size_t)(kb & 1) * STAGE2;
        char* pA = st;
        char* pB = st + ARR2_BYTES;
#pragma unroll
        for (int kk = 0; kk < 64; kk += 16) {
            uint32_t afr[4][4], bh[4][2];
#pragma unroll
            for (int p = 0; p < 2; p++) {
                int bn = wn + p * 16 + ((lane >> 4) << 3) + (lane & 7);
                int bk = kk + ((lane >> 3) & 1) * 8;
                uint32_t r0, r1, r2, r3;
                ldsm4(r0, r1, r2, r3, smem_u32(pB + bn * PITCH2 + bk * 2));
                bh[p * 2][0] = r0; bh[p * 2][1] = r1;
                bh[p * 2 + 1][0] = r2; bh[p * 2 + 1][1] = r3;
            }
#pragma unroll
            for (int mi = 0; mi < 4; mi++) {
                int row = wm + mi * 16 + (lane & 15);
                int col = kk + (lane >> 4) * 8;
                ldsm4(afr[mi][0], afr[mi][1], afr[mi][2], afr[mi][3],
                      smem_u32(pA + row * PITCH2 + col * 2));
            }
#pragma unroll
            for (int mi = 0; mi < 4; mi++)
#pragma unroll
                for (int ni = 0; ni < 4; ni++)
                    mma_fp16(acc[mi][ni], afr[mi], bh[ni]);
        }
    }

#pragma unroll
    for (int mi = 0; mi < 4; mi++) {
        int gr0 = rowbase + wm + mi * 16 + (lane >> 2);
        int gr1 = gr0 + 8;
#pragma unroll
        for (int ni = 0; ni < 4; ni++) {
            int col = nt * 128 + wn + ni * 8 + (lane & 3) * 2;
            if (gr0 < cnt) {
                float2 v = make_float2(acc[mi][ni][0] * WINV, acc[mi][ni][1] * WINV);
                *(float2*)&d_y[(size_t)(off + gr0) * H_DIM + col] = v;
            }
            if (gr1 < cnt) {
                float2 v = make_float2(acc[mi][ni][2] * WINV, acc[mi][ni][3] * WINV);
                *(float2*)&d_y[(size_t)(off + gr1) * H_DIM + col] = v;
            }
        }
    }
}

// ---------------- launch 7: combine + re-zero counters for next replay ----------------
__global__ void k_combine(float* __restrict__ out) {
    if (blockIdx.x == 0 && threadIdx.x < E_NUM) d_count[threadIdx.x] = 0;
    size_t idx = (size_t)blockIdx.x * 256 + threadIdx.x;   // one float4 of out
    const int H4 = H_DIM / 4;
    int t = (int)(idx / H4);
    int c = (int)(idx % H4);
    int p0 = d_pos[2 * t], p1 = d_pos[2 * t + 1];
    float w0 = d_tok_w[2 * t], w1 = d_tok_w[2 * t + 1];
    const float4* y = (const float4*)d_y;
    float4 a = y[(size_t)p0 * H4 + c];
    float4 b = y[(size_t)p1 * H4 + c];
    float4 o;
    o.x = w0 * a.x + w1 * b.x;
    o.y = w0 * a.y + w1 * b.y;
    o.z = w0 * a.z + w1 * b.z;
    o.w = w0 * a.w + w1 * b.w;
    ((float4*)out)[idx] = o;
}

// ---------------- launch ----------------
extern "C" void kernel_launch(void* const* d_in, const int* in_sizes, int n_in,
                              void* d_out, int out_size) {
    const float* x  = (const float*)d_in[0];   // [T, H]
    const float* gw = (const float*)d_in[1];   // [E, H]
    const float* wg = (const float*)d_in[2];   // [E, H, I]
    const float* wu = (const float*)d_in[3];   // [E, H, I]
    const float* wd = (const float*)d_in[4];   // [E, I, H]
    float* out = (float*)d_out;                // [T, H]

    cudaFuncSetAttribute(k_gemm1, cudaFuncAttributeMaxDynamicSharedMemorySize, SMEM_DYN);
    cudaFuncSetAttribute(k_gemm2, cudaFuncAttributeMaxDynamicSharedMemorySize, SMEM2);

    k_router<<<T_TOK / 8, 256>>>(x, gw);                                     // 1
    k_convx<<<(int)((size_t)T_TOK * H_DIM / 4 / 256), 256>>>(x);             // 2
    k_w1t<<<dim3(I_DIM / 32, H_DIM / 32, E_NUM * 2), dim3(32, 8)>>>(wg, wu); // 3
    k_gemm1<<<dim3(NI2 / 128, CAP / 128, E_NUM), 256, SMEM_DYN>>>();         // 4 <- profiled
    k_w2t<<<dim3(H_DIM / 32, I_DIM / 32, E_NUM), dim3(32, 8)>>>(wd);         // 5
    k_gemm2<<<dim3(H_DIM / 128, CAP / 128, E_NUM), 256, SMEM2>>>();          // 6
    k_combine<<<(int)((size_t)T_TOK * H_DIM / 4 / 256), 256>>>(out);         // 7
}

// round 11
// speedup vs baseline: 3.2177x; 1.4916x over previous
#include <cuda_runtime.h>
#include <cuda_bf16.h>
#include <cuda_fp16.h>
#include <cstdint>

#define T_TOK 8192
#define H_DIM 2048
#define I_DIM 1408
#define E_NUM 8
#define NI2   (2 * I_DIM)   // 2816 interleaved gate/up columns
#define CAP   8192          // max rows per expert (top-2 of distinct experts)
#define WSCALE 64.0f
#define WINV   (1.0f / 64.0f)

// ---------------- scratch (device globals; no allocations) ----------------
__device__ int   d_count[E_NUM];                 // zero at load; re-zeroed by k_combine
__device__ float d_tok_w[T_TOK * 2];
__device__ int   d_pos[T_TOK * 2];               // token,k -> row in per-expert region
__device__ int   d_pair_slot[E_NUM * CAP];       // row -> tok*2+k

__device__ __align__(16) __half d_xh[(size_t)T_TOK * H_DIM];                 // x fp16
__device__ __align__(16) __half d_w1hi[(size_t)E_NUM * NI2 * H_DIM];         // W1*64 fp16 (single-pass)
__device__ __align__(16) __half d_w2hi[(size_t)E_NUM * H_DIM * I_DIM];       // W2^T*64 fp16 (single-pass)
__device__ __align__(16) __half d_h[(size_t)E_NUM * CAP * I_DIM];            // activations fp16
__device__ __align__(16) float  d_y[(size_t)E_NUM * CAP * H_DIM];

// ---------------- helpers ----------------
static __device__ __forceinline__ uint32_t smem_u32(const void* p) {
    return (uint32_t)__cvta_generic_to_shared(p);
}
static __device__ __forceinline__ void ldsm4(uint32_t& r0, uint32_t& r1, uint32_t& r2, uint32_t& r3, uint32_t a) {
    asm volatile("ldmatrix.sync.aligned.m8n8.x4.shared.b16 {%0,%1,%2,%3},[%4];"
                 : "=r"(r0), "=r"(r1), "=r"(r2), "=r"(r3) : "r"(a));
}
static __device__ __forceinline__ void mma_fp16(float* c, const uint32_t* a, const uint32_t* b) {
    asm volatile("mma.sync.aligned.m16n8k16.row.col.f32.f16.f16.f32 "
                 "{%0,%1,%2,%3},{%4,%5,%6,%7},{%8,%9},{%0,%1,%2,%3};"
                 : "+f"(c[0]), "+f"(c[1]), "+f"(c[2]), "+f"(c[3])
                 : "r"(a[0]), "r"(a[1]), "r"(a[2]), "r"(a[3]), "r"(b[0]), "r"(b[1]));
}
static __device__ __forceinline__ void cpa16(uint32_t s, const void* g, int sz) {
    asm volatile("cp.async.cg.shared.global [%0], [%1], 16, %2;" :: "r"(s), "l"(g), "r"(sz));
}

// shared GEMM smem geometry: 2 arrays per stage (A, B), each 128 rows x 64 halfs, 144B pitch
#define PITCH2      144
#define ARR2_BYTES  (128 * PITCH2)            // 18432
#define STAGE2      (2 * ARR2_BYTES)          // 36864
#define SMEM2       (512 + 2 * STAGE2)        // 74240

// ---------------- launch 1: router (fused compaction via per-expert capacity) ----------------
__global__ void k_router(const float* __restrict__ x, const float* __restrict__ gw) {
    int warp = (blockIdx.x * blockDim.x + threadIdx.x) >> 5;
    int lane = threadIdx.x & 31;
    if (warp >= T_TOK) return;
    const float* xr = x + (size_t)warp * H_DIM;
    float acc[E_NUM];
#pragma unroll
    for (int e = 0; e < E_NUM; e++) acc[e] = 0.f;
    for (int i = lane; i < H_DIM; i += 32) {
        float xv = xr[i];
#pragma unroll
        for (int e = 0; e < E_NUM; e++) acc[e] += xv * gw[e * H_DIM + i];
    }
#pragma unroll
    for (int e = 0; e < E_NUM; e++)
#pragma unroll
        for (int o = 16; o > 0; o >>= 1) acc[e] += __shfl_xor_sync(0xffffffffu, acc[e], o);
    if (lane == 0) {
        float m = acc[0];
#pragma unroll
        for (int e = 1; e < E_NUM; e++) m = fmaxf(m, acc[e]);
        float p[E_NUM];
#pragma unroll
        for (int e = 0; e < E_NUM; e++) p[e] = __expf(acc[e] - m);
        int e0 = 0; float w0 = p[0];
#pragma unroll
        for (int e = 1; e < E_NUM; e++) if (p[e] > w0) { w0 = p[e]; e0 = e; }
        int e1 = -1; float w1 = -1.f;
#pragma unroll
        for (int e = 0; e < E_NUM; e++) if (e != e0 && p[e] > w1) { w1 = p[e]; e1 = e; }
        float inv = 1.f / (w0 + w1);
        d_tok_w[warp * 2 + 0] = w0 * inv;
        d_tok_w[warp * 2 + 1] = w1 * inv;
        int p0 = e0 * CAP + atomicAdd(&d_count[e0], 1);
        int p1 = e1 * CAP + atomicAdd(&d_count[e1], 1);
        d_pair_slot[p0] = warp * 2 + 0;  d_pos[warp * 2 + 0] = p0;
        d_pair_slot[p1] = warp * 2 + 1;  d_pos[warp * 2 + 1] = p1;
    }
}

// ---------------- launch 2: x -> fp16 ----------------
__global__ void k_convx(const float* __restrict__ x) {
    size_t idx = (size_t)blockIdx.x * 256 + threadIdx.x;        // one float4
    float4 v = ((const float4*)x)[idx];
    ((__half2*)d_xh)[2 * idx + 0] = __floats2half2_rn(v.x, v.y);
    ((__half2*)d_xh)[2 * idx + 1] = __floats2half2_rn(v.z, v.w);
}

// ---------------- launch 3: W1 transpose+interleave -> [e][2i+mat][H], *64, fp16 ----------------
__global__ void k_w1t(const float* __restrict__ wg, const float* __restrict__ wu) {
    __shared__ float tile[32][33];
    int mat = blockIdx.z & 1, e = blockIdx.z >> 1;
    const float* src = (mat ? wu : wg) + (size_t)e * H_DIM * I_DIM;
    int i0 = blockIdx.x * 32, h0 = blockIdx.y * 32;
    int tx = threadIdx.x, ty = threadIdx.y;
#pragma unroll
    for (int j = 0; j < 4; j++)
        tile[ty + 8 * j][tx] = src[(size_t)(h0 + ty + 8 * j) * I_DIM + i0 + tx];
    __syncthreads();
#pragma unroll
    for (int j = 0; j < 4; j++) {
        int oi = i0 + ty + 8 * j, oh = h0 + tx;
        float v = tile[tx][ty + 8 * j] * WSCALE;
        size_t o = ((size_t)e * NI2 + 2 * oi + mat) * H_DIM + oh;
        d_w1hi[o] = __float2half_rn(v);
    }
}

// ---------------- launch 5: Wdown transpose -> [e][h][i], *64, fp16 ----------------
__global__ void k_w2t(const float* __restrict__ wd) {
    __shared__ float tile[32][33];
    int e = blockIdx.z;
    const float* src = wd + (size_t)e * I_DIM * H_DIM;
    int h0 = blockIdx.x * 32, i0 = blockIdx.y * 32;
    int tx = threadIdx.x, ty = threadIdx.y;
#pragma unroll
    for (int j = 0; j < 4; j++)
        tile[ty + 8 * j][tx] = src[(size_t)(i0 + ty + 8 * j) * H_DIM + h0 + tx];
    __syncthreads();
#pragma unroll
    for (int j = 0; j < 4; j++) {
        int oh = h0 + ty + 8 * j, oi = i0 + tx;
        float v = tile[tx][ty + 8 * j] * WSCALE;
        size_t o = ((size_t)e * H_DIM + oh) * I_DIM + oi;
        d_w2hi[o] = __float2half_rn(v);
    }
}

// ---------------- single-pass 64-K compute slab, warp tile 64x32 ----------------
#define COMPUTE_SLAB64(pA, pB)                                                          \
    _Pragma("unroll")                                                                   \
    for (int kk = 0; kk < 64; kk += 16) {                                               \
        uint32_t afr[4][4], bh[4][2];                                                   \
        _Pragma("unroll")                                                               \
        for (int p = 0; p < 2; p++) {                                                   \
            int bn = wn + p * 16 + ((lane >> 4) << 3) + (lane & 7);                     \
            int bk = kk + ((lane >> 3) & 1) * 8;                                        \
            uint32_t r0, r1, r2, r3;                                                    \
            ldsm4(r0, r1, r2, r3, smem_u32(pB + bn * PITCH2 + bk * 2));                 \
            bh[p * 2][0] = r0; bh[p * 2][1] = r1;                                       \
            bh[p * 2 + 1][0] = r2; bh[p * 2 + 1][1] = r3;                               \
        }                                                                               \
        _Pragma("unroll")                                                               \
        for (int mi = 0; mi < 4; mi++) {                                                \
            int row = wm + mi * 16 + (lane & 15);                                       \
            int col = kk + (lane >> 4) * 8;                                             \
            ldsm4(afr[mi][0], afr[mi][1], afr[mi][2], afr[mi][3],                       \
                  smem_u32(pA + row * PITCH2 + col * 2));                               \
        }                                                                               \
        _Pragma("unroll")                                                               \
        for (int mi = 0; mi < 4; mi++)                                                  \
            _Pragma("unroll")                                                           \
            for (int ni = 0; ni < 4; ni++)                                              \
                mma_fp16(acc[mi][ni], afr[mi], bh[ni]);                                 \
    }

// ---------------- launch 4 (PROFILED): GEMM1 gathered X @ [Wgate ⧉ Wup]*64 -> h ----------------
__global__ void __launch_bounds__(256, 2) k_gemm1() {
    extern __shared__ char smem[];
    int e = blockIdx.z;
    int cnt = d_count[e];
    int rowbase = blockIdx.y * 128;
    if (rowbase >= cnt) return;
    int off = e * CAP, ct = blockIdx.x;
    int tid = threadIdx.x, warp = tid >> 5, lane = tid & 31;
    int wm = (warp & 1) * 64, wn = (warp >> 1) * 32;

    int* sTok = (int*)smem;
    if (tid < 128) {
        int gr = rowbase + tid;
        sTok[tid] = (gr < cnt) ? (d_pair_slot[off + gr] >> 1) : -1;
    }
    __syncthreads();

    const __half* wbH = d_w1hi + ((size_t)e * NI2 + (size_t)ct * 128) * H_DIM;

    float acc[4][4][4];
#pragma unroll
    for (int mi = 0; mi < 4; mi++)
#pragma unroll
        for (int ni = 0; ni < 4; ni++)
#pragma unroll
            for (int j = 0; j < 4; j++) acc[mi][ni][j] = 0.f;

    const int NKB = H_DIM / 64;   // 32
    auto issue = [&](int kb) {
        char* st = smem + 512 + (size_t)(kb & 1) * STAGE2;
        int k0 = kb * 64;
#pragma unroll
        for (int i = 0; i < 8; i++) {
            int idx = tid + i * 256;
            int c = idx & 7, r = (idx >> 3) & 127, arr = idx >> 10;
            uint32_t sa = smem_u32(st + arr * ARR2_BYTES + r * PITCH2 + c * 16);
            const __half* g; int sz = 16;
            if (arr == 0) {
                int tok = sTok[r];
                if (tok < 0) { tok = 0; sz = 0; }
                g = d_xh + (size_t)tok * H_DIM + k0 + c * 8;
            } else {
                g = wbH + (size_t)r * H_DIM + k0 + c * 8;
            }
            cpa16(sa, g, sz);
        }
        asm volatile("cp.async.commit_group;");
    };

    issue(0);
    for (int kb = 0; kb < NKB; kb++) {
        asm volatile("cp.async.wait_group 0;" ::: "memory");
        __syncthreads();
        if (kb + 1 < NKB) issue(kb + 1);
        char* st = smem + 512 + (size_t)(kb & 1) * STAGE2;
        char* pA = st;
        char* pB = st + ARR2_BYTES;
        COMPUTE_SLAB64(pA, pB);
    }

    // epilogue: (c0,c1) = (gate, up)*64 at same h column; unscale BEFORE silu
#pragma unroll
    for (int mi = 0; mi < 4; mi++) {
        int gr0 = rowbase + wm + mi * 16 + (lane >> 2);
        int gr1 = gr0 + 8;
#pragma unroll
        for (int ni = 0; ni < 4; ni++) {
            int ncol = wn + ni * 8 + (lane & 3) * 2;
            int hc = ct * 64 + (ncol >> 1);
            if (gr0 < cnt) {
                float g = acc[mi][ni][0] * WINV, u = acc[mi][ni][1] * WINV;
                float y = u * g / (1.f + __expf(-g));
                d_h[(size_t)(off + gr0) * I_DIM + hc] = __float2half_rn(y);
            }
            if (gr1 < cnt) {
                float g = acc[mi][ni][2] * WINV, u = acc[mi][ni][3] * WINV;
                float y = u * g / (1.f + __expf(-g));
                d_h[(size_t)(off + gr1) * I_DIM + hc] = __float2half_rn(y);
            }
        }
    }
}

// ---------------- launch 6: GEMM2 h @ (Wdown*64)^T -> y (single-pass, 64-K slabs) ----------------
__global__ void __launch_bounds__(256, 2) k_gemm2() {
    extern __shared__ char smem[];
    int e = blockIdx.z;
    int cnt = d_count[e];
    int rowbase = blockIdx.y * 128;
    if (rowbase >= cnt) return;
    int off = e * CAP, nt = blockIdx.x;
    int tid = threadIdx.x, warp = tid >> 5, lane = tid & 31;
    int wm = (warp & 1) * 64, wn = (warp >> 1) * 32;

    const __half* wbH = d_w2hi + ((size_t)e * H_DIM + (size_t)nt * 128) * I_DIM;
    const __half* aH0 = d_h + (size_t)(off + rowbase) * I_DIM;

    float acc[4][4][4];
#pragma unroll
    for (int mi = 0; mi < 4; mi++)
#pragma unroll
        for (int ni = 0; ni < 4; ni++)
#pragma unroll
            for (int j = 0; j < 4; j++) acc[mi][ni][j] = 0.f;

    const int NKB = I_DIM / 64;   // 22
    auto issue = [&](int kb) {
        char* st = smem + 512 + (size_t)(kb & 1) * STAGE2;
        int k0 = kb * 64;
#pragma unroll
        for (int i = 0; i < 8; i++) {
            int idx = tid + i * 256;
            int c = idx & 7, r = (idx >> 3) & 127, arr = idx >> 10;
            uint32_t sa = smem_u32(st + arr * ARR2_BYTES + r * PITCH2 + c * 16);
            const __half* g; int sz = 16;
            if (arr == 0) {
                if (rowbase + r >= cnt) sz = 0;
                g = aH0 + (size_t)r * I_DIM + k0 + c * 8;
            } else {
                g = wbH + (size_t)r * I_DIM + k0 + c * 8;
            }
            cpa16(sa, g, sz);
        }
        asm volatile("cp.async.commit_group;");
    };

    issue(0);
    for (int kb = 0; kb < NKB; kb++) {
        asm volatile("cp.async.wait_group 0;" ::: "memory");
        __syncthreads();
        if (kb + 1 < NKB) issue(kb + 1);
        char* st = smem + 512 + (size_t)(kb & 1) * STAGE2;
        char* pA = st;
        char* pB = st + ARR2_BYTES;
        COMPUTE_SLAB64(pA, pB);
    }

#pragma unroll
    for (int mi = 0; mi < 4; mi++) {
        int gr0 = rowbase + wm + mi * 16 + (lane >> 2);
        int gr1 = gr0 + 8;
#pragma unroll
        for (int ni = 0; ni < 4; ni++) {
            int col = nt * 128 + wn + ni * 8 + (lane & 3) * 2;
            if (gr0 < cnt) {
                float2 v = make_float2(acc[mi][ni][0] * WINV, acc[mi][ni][1] * WINV);
                *(float2*)&d_y[(size_t)(off + gr0) * H_DIM + col] = v;
            }
            if (gr1 < cnt) {
                float2 v = make_float2(acc[mi][ni][2] * WINV, acc[mi][ni][3] * WINV);
                *(float2*)&d_y[(size_t)(off + gr1) * H_DIM + col] = v;
            }
        }
    }
}

// ---------------- launch 7: combine + re-zero counters for next replay ----------------
__global__ void k_combine(float* __restrict__ out) {
    if (blockIdx.x == 0 && threadIdx.x < E_NUM) d_count[threadIdx.x] = 0;
    size_t idx = (size_t)blockIdx.x * 256 + threadIdx.x;   // one float4 of out
    const int H4 = H_DIM / 4;
    int t = (int)(idx / H4);
    int c = (int)(idx % H4);
    int p0 = d_pos[2 * t], p1 = d_pos[2 * t + 1];
    float w0 = d_tok_w[2 * t], w1 = d_tok_w[2 * t + 1];
    const float4* y = (const float4*)d_y;
    float4 a = y[(size_t)p0 * H4 + c];
    float4 b = y[(size_t)p1 * H4 + c];
    float4 o;
    o.x = w0 * a.x + w1 * b.x;
    o.y = w0 * a.y + w1 * b.y;
    o.z = w0 * a.z + w1 * b.z;
    o.w = w0 * a.w + w1 * b.w;
    ((float4*)out)[idx] = o;
}

// ---------------- launch ----------------
extern "C" void kernel_launch(void* const* d_in, const int* in_sizes, int n_in,
                              void* d_out, int out_size) {
    const float* x  = (const float*)d_in[0];   // [T, H]
    const float* gw = (const float*)d_in[1];   // [E, H]
    const float* wg = (const float*)d_in[2];   // [E, H, I]
    const float* wu = (const float*)d_in[3];   // [E, H, I]
    const float* wd = (const float*)d_in[4];   // [E, I, H]
    float* out = (float*)d_out;                // [T, H]

    cudaFuncSetAttribute(k_gemm1, cudaFuncAttributeMaxDynamicSharedMemorySize, SMEM2);
    cudaFuncSetAttribute(k_gemm2, cudaFuncAttributeMaxDynamicSharedMemorySize, SMEM2);

    k_router<<<T_TOK / 8, 256>>>(x, gw);                                     // 1
    k_convx<<<(int)((size_t)T_TOK * H_DIM / 4 / 256), 256>>>(x);             // 2
    k_w1t<<<dim3(I_DIM / 32, H_DIM / 32, E_NUM * 2), dim3(32, 8)>>>(wg, wu); // 3
    k_gemm1<<<dim3(NI2 / 128, CAP / 128, E_NUM), 256, SMEM2>>>();            // 4 <- profiled
    k_w2t<<<dim3(H_DIM / 32, I_DIM / 32, E_NUM), dim3(32, 8)>>>(wd);         // 5
    k_gemm2<<<dim3(H_DIM / 128, CAP / 128, E_NUM), 256, SMEM2>>>();          // 6
    k_combine<<<(int)((size_t)T_TOK * H_DIM / 4 / 256), 256>>>(out);         // 7
}